// round 6
// baseline (speedup 1.0000x reference)
#include <cuda_runtime.h>
#include <cuda_bf16.h>
#include <math.h>
#include <stdint.h>

#define B_SZ 2048
#define L_SZ 64
#define D_SZ 256
#define U_SZ 512

#define PITCH 264                     // bf16 elems per row (256 + 8 pad): conflict-free LDSM
#define CH_ROWS 32                    // u-rows per B chunk
#define N_CHUNKS 16                   // 512 / 32
#define CH_BYTES (CH_ROWS * PITCH * 2)   // 16896

// ---------------------------------------------------------------------------
// PTX helpers (base-PTX only; compiles under compute_103)
// ---------------------------------------------------------------------------
__device__ __forceinline__ uint32_t smem_to_u32(const void* p) {
    uint32_t a;
    asm("{ .reg .u64 t; cvta.to.shared.u64 t, %1; cvt.u32.u64 %0, t; }"
        : "=r"(a) : "l"(p));
    return a;
}

#define MBARRIER_INIT(mb, c) \
    asm volatile("mbarrier.init.shared.b64 [%0], %1;" \
                 :: "r"((uint32_t)(mb)), "r"((uint32_t)(c)) : "memory")
#define MBARRIER_INVAL(mb) \
    asm volatile("mbarrier.inval.shared.b64 [%0];" :: "r"((uint32_t)(mb)) : "memory")
#define MBARRIER_EXPECT_TX(mb, bytes) \
    asm volatile("mbarrier.arrive.expect_tx.shared.b64 _, [%0], %1;" \
                 :: "r"((uint32_t)(mb)), "r"((uint32_t)(bytes)) : "memory")

#define MBARRIER_WAIT_PARITY(mb, ph) do { \
    uint32_t _mb = (uint32_t)(mb); uint32_t _p = (uint32_t)(ph); uint32_t _done; \
    asm volatile("{\n\t.reg .pred p;\n\t" \
        "mbarrier.try_wait.parity.acquire.cta.shared::cta.b64 p, [%1], %2;\n\t" \
        "selp.b32 %0, 1, 0, p;\n\t}" : "=r"(_done) : "r"(_mb), "r"(_p) : "memory"); \
    if (!_done) { \
        asm volatile("{\n\t.reg .pred P1;\n\t" \
            "WL_%=:\n\t" \
            "mbarrier.try_wait.parity.acquire.cta.shared::cta.b64 P1, [%0], %1, 0x989680;\n\t" \
            "@P1 bra.uni WD_%=;\n\t" \
            "bra.uni WL_%=;\n\t" \
            "WD_%=:\n\t}" :: "r"(_mb), "r"(_p) : "memory"); \
    } \
} while (0)

// 1D bulk async copy gmem -> smem (TMA engine)
#define BULK_G2S(dst, src, sz, mb) \
    asm volatile("cp.async.bulk.shared::cluster.global.mbarrier::complete_tx::bytes " \
                 "[%0], [%1], %2, [%3];" \
                 :: "r"((uint32_t)(dst)), "l"(src), "r"((uint32_t)(sz)), \
                    "r"((uint32_t)(mb)) : "memory")

#define LDMX4(r0, r1, r2, r3, addr) \
    asm volatile("ldmatrix.sync.aligned.m8n8.x4.shared.b16 {%0,%1,%2,%3}, [%4];" \
                 : "=r"(r0), "=r"(r1), "=r"(r2), "=r"(r3) : "r"(addr))

#define MMA16816(c, a0, a1, a2, a3, b0, b1) \
    asm volatile("mma.sync.aligned.m16n8k16.row.col.f32.bf16.bf16.f32 " \
                 "{%0,%1,%2,%3},{%4,%5,%6,%7},{%8,%9},{%0,%1,%2,%3};" \
                 : "+f"((c)[0]), "+f"((c)[1]), "+f"((c)[2]), "+f"((c)[3]) \
                 : "r"(a0), "r"(a1), "r"(a2), "r"(a3), "r"(b0), "r"(b1))

__device__ __forceinline__ float tanh_fast(float x) {
    float e = __expf(2.f * x);
    return 1.f - __fdividef(2.f, e + 1.f);
}

// ---------------------------------------------------------------------------
// Device scratch (allocation-free)
// ---------------------------------------------------------------------------
__device__ float g_ph[B_SZ * U_SZ];
__device__ __align__(16) unsigned char g_w1t_hi[N_CHUNKS * CH_BYTES];
__device__ __align__(16) unsigned char g_w1t_lo[N_CHUNKS * CH_BYTES];

// ---------------------------------------------------------------------------
// Prep: W1[d][u] -> chunked W1^T (bf16 hi/lo), rows n=u%32, cols k=d, pitch 264
// ---------------------------------------------------------------------------
__global__ void prep_w1_kernel(const float* __restrict__ W1) {
    const int d = blockIdx.x;
    const int u = threadIdx.x;
    const float f = W1[(size_t)d * U_SZ + u];
    const __nv_bfloat16 hi = __float2bfloat16(f);
    const __nv_bfloat16 lo = __float2bfloat16(f - __bfloat162float(hi));
    const int chunk = u >> 5, n = u & 31;
    const size_t off = (size_t)chunk * CH_BYTES + ((size_t)n * PITCH + d) * 2;
    *(__nv_bfloat16*)(g_w1t_hi + off) = hi;
    *(__nv_bfloat16*)(g_w1t_lo + off) = lo;
}

// ---------------------------------------------------------------------------
// proj_h: g_ph[b][u] = hidden[b,:].W2[:,u] + b1[u] + b2[u]
// ---------------------------------------------------------------------------
__global__ void proj_h_kernel(const float* __restrict__ hidden,
                              const float* __restrict__ W2,
                              const float* __restrict__ b1,
                              const float* __restrict__ b2)
{
    __shared__ float As[16][65];
    __shared__ float Bs[16][68];
    const int tid  = threadIdx.x;
    const int row0 = blockIdx.y * 64;
    const int col0 = blockIdx.x * 64;
    const int tr   = tid >> 4;
    const int tc   = tid & 15;

    float acc[4][4];
#pragma unroll
    for (int i = 0; i < 4; ++i)
#pragma unroll
        for (int j = 0; j < 4; ++j) acc[i][j] = 0.f;

    for (int k0 = 0; k0 < U_SZ; k0 += 16) {
#pragma unroll
        for (int t = 0; t < 4; ++t) {
            int idx = tid + 256 * t;
            As[idx & 15][idx >> 4] =
                hidden[(size_t)(row0 + (idx >> 4)) * U_SZ + k0 + (idx & 15)];
        }
#pragma unroll
        for (int t = 0; t < 4; ++t) {
            int idx = tid + 256 * t;
            Bs[idx >> 6][idx & 63] =
                W2[(size_t)(k0 + (idx >> 6)) * U_SZ + col0 + (idx & 63)];
        }
        __syncthreads();
#pragma unroll
        for (int k = 0; k < 16; ++k) {
            float a[4], bb[4];
#pragma unroll
            for (int i = 0; i < 4; ++i) a[i] = As[k][tr * 4 + i];
#pragma unroll
            for (int j = 0; j < 4; ++j) bb[j] = Bs[k][tc * 4 + j];
#pragma unroll
            for (int i = 0; i < 4; ++i)
#pragma unroll
                for (int j = 0; j < 4; ++j) acc[i][j] = fmaf(a[i], bb[j], acc[i][j]);
        }
        __syncthreads();
    }
#pragma unroll
    for (int i = 0; i < 4; ++i)
#pragma unroll
        for (int j = 0; j < 4; ++j) {
            int n = col0 + tc * 4 + j;
            g_ph[(size_t)(row0 + tr * 4 + i) * U_SZ + n] = acc[i][j] + b1[n] + b2[n];
        }
}

// ---------------------------------------------------------------------------
// Main fused kernel: 1 CTA = 2 batches (M=128 rows), 8 warps x 16 rows.
// A fragments in registers; SEPARATE accumulators per bf16x3 product so all
// HMMA chains are independent (12 streams/warp).
// SMEM byte offsets:
static constexpr int SA_HI = 0;                       // 67584
static constexpr int SA_LO = 67584;                   // 67584
static constexpr int SB    = 135168;                  // 2 bufs x (hi+lo)
static constexpr int BUF_STRIDE = 2 * CH_BYTES;       // 33792
static constexpr int SPH   = 202752;                  // 4096
static constexpr int SV    = 206848;                  // 2048
static constexpr int SW    = 208896;                  // 512
static constexpr int SRED  = 209408;                  // 32
static constexpr int SMBAR = 209440;                  // 2 x 8B
static constexpr int SMEM_TOTAL = 209472;
// ---------------------------------------------------------------------------
__global__ void __launch_bounds__(256, 1)
attn_mma_kernel(const float* __restrict__ features,
                const float* __restrict__ V,
                float* __restrict__ ctx_out,
                float* __restrict__ w_out)
{
    extern __shared__ __align__(1024) char smem[];
    const uint32_t smem_u = smem_to_u32(smem);
    const int tid  = threadIdx.x;
    const int wid  = tid >> 5;
    const int lane = tid & 31;
    const int b0   = blockIdx.x * 2;

    float* ph_s  = (float*)(smem + SPH);
    float* V_s   = (float*)(smem + SV);
    float* w_s   = (float*)(smem + SW);
    float* red_s = (float*)(smem + SRED);

    // ---- mbarriers + kick off first two B-chunk bulk copies ----
    if (tid == 0) {
        MBARRIER_INIT(smem_u + SMBAR, 1);
        MBARRIER_INIT(smem_u + SMBAR + 8, 1);
#pragma unroll
        for (int c = 0; c < 2; ++c) {
            const uint32_t mb = smem_u + SMBAR + 8 * c;
            const uint32_t bh = smem_u + SB + c * BUF_STRIDE;
            MBARRIER_EXPECT_TX(mb, 2 * CH_BYTES);
            BULK_G2S(bh,            g_w1t_hi + (size_t)c * CH_BYTES, CH_BYTES, mb);
            BULK_G2S(bh + CH_BYTES, g_w1t_lo + (size_t)c * CH_BYTES, CH_BYTES, mb);
        }
    }

    // ---- Stage features[b0..b0+1] as bf16 hi/lo (padded rows) ----
    {
        const float4* fsrc = (const float4*)(features + (size_t)b0 * L_SZ * D_SZ);
#pragma unroll 4
        for (int t = 0; t < 32; ++t) {
            const int idx = tid + 256 * t;
            const int row = idx >> 6;
            const int d   = (idx & 63) * 4;
            const float4 v = fsrc[idx];
            __nv_bfloat162 h0 = __float22bfloat162_rn(make_float2(v.x, v.y));
            __nv_bfloat162 h1 = __float22bfloat162_rn(make_float2(v.z, v.w));
            __nv_bfloat162 l0 = __float22bfloat162_rn(make_float2(
                v.x - __bfloat162float(h0.x), v.y - __bfloat162float(h0.y)));
            __nv_bfloat162 l1 = __float22bfloat162_rn(make_float2(
                v.z - __bfloat162float(h1.x), v.w - __bfloat162float(h1.y)));
            const uint32_t off = ((uint32_t)row * PITCH + d) * 2;
            *(uint2*)(smem + SA_HI + off) =
                make_uint2(*(uint32_t*)&h0, *(uint32_t*)&h1);
            *(uint2*)(smem + SA_LO + off) =
                make_uint2(*(uint32_t*)&l0, *(uint32_t*)&l1);
        }
    }
#pragma unroll
    for (int t = 0; t < 4; ++t)
        ph_s[tid + 256 * t] = g_ph[(size_t)b0 * U_SZ + tid + 256 * t];
    V_s[tid]       = V[tid];
    V_s[tid + 256] = V[tid + 256];
    __syncthreads();

    // ---- ldmatrix address components ----
    const int m0 = wid * 16;
    const uint32_t a_row = (uint32_t)(m0 + (lane & 7) + ((lane >> 3) & 1) * 8);
    const uint32_t a_off = (a_row * PITCH + ((uint32_t)(lane >> 4)) * 8) * 2;
    const uint32_t b4_off = (((uint32_t)(lane & 7) + (((uint32_t)lane >> 4) & 1) * 8) * PITCH) * 2
                          + (((uint32_t)lane >> 3) & 1) * 16;
    const int phb = (wid >> 2) * U_SZ;

    // ---- Preload ALL A fragments into registers ----
    uint32_t ah[16][4], al[16][4];
#pragma unroll
    for (int kk = 0; kk < 16; ++kk) {
        const uint32_t koff = (uint32_t)kk * 32;
        LDMX4(ah[kk][0], ah[kk][1], ah[kk][2], ah[kk][3],
              smem_u + SA_HI + a_off + koff);
        LDMX4(al[kk][0], al[kk][1], al[kk][2], al[kk][3],
              smem_u + SA_LO + a_off + koff);
    }

    float pl0 = 0.f, pl1 = 0.f;

    // ==================== chunk loop ====================
    for (int c = 0; c < N_CHUNKS; ++c) {
        const uint32_t mb = smem_u + SMBAR + 8 * (c & 1);
        MBARRIER_WAIT_PARITY(mb, (c >> 1) & 1);

        const uint32_t bh = smem_u + SB + (c & 1) * BUF_STRIDE;
        const uint32_t bl = bh + CH_BYTES;

        // Separate accumulators per product: 12 independent HMMA chains.
        float acc_hh[4][4], acc_hl[4][4], acc_lh[4][4];
#pragma unroll
        for (int j = 0; j < 4; ++j)
#pragma unroll
            for (int r = 0; r < 4; ++r) {
                acc_hh[j][r] = 0.f; acc_hl[j][r] = 0.f; acc_lh[j][r] = 0.f;
            }

#pragma unroll
        for (int kk = 0; kk < 16; ++kk) {
            const uint32_t koff = (uint32_t)kk * 32;
#pragma unroll
            for (int j2 = 0; j2 < 2; ++j2) {
                const uint32_t jb = b4_off + (uint32_t)j2 * (16 * PITCH * 2) + koff;
                uint32_t bh0, bh1, bh2, bh3, bl0, bl1, bl2, bl3;
                LDMX4(bh0, bh1, bh2, bh3, bh + jb);
                LDMX4(bl0, bl1, bl2, bl3, bl + jb);
                const int j = j2 * 2;
                MMA16816(acc_hh[j],     ah[kk][0], ah[kk][1], ah[kk][2], ah[kk][3], bh0, bh1);
                MMA16816(acc_hh[j + 1], ah[kk][0], ah[kk][1], ah[kk][2], ah[kk][3], bh2, bh3);
                MMA16816(acc_hl[j],     ah[kk][0], ah[kk][1], ah[kk][2], ah[kk][3], bl0, bl1);
                MMA16816(acc_hl[j + 1], ah[kk][0], ah[kk][1], ah[kk][2], ah[kk][3], bl2, bl3);
                MMA16816(acc_lh[j],     al[kk][0], al[kk][1], al[kk][2], al[kk][3], bh0, bh1);
                MMA16816(acc_lh[j + 1], al[kk][0], al[kk][1], al[kk][2], al[kk][3], bh2, bh3);
            }
        }

        // fused epilogue for this chunk's u-columns
#pragma unroll
        for (int j = 0; j < 4; ++j) {
            const int u = c * 32 + j * 8 + (lane & 3) * 2;
            const float ph0 = ph_s[phb + u],     vv0 = V_s[u];
            const float ph1 = ph_s[phb + u + 1], vv1 = V_s[u + 1];
            pl0 = fmaf(vv0, tanh_fast(acc_hh[j][0] + acc_hl[j][0] + acc_lh[j][0] + ph0), pl0);
            pl0 = fmaf(vv1, tanh_fast(acc_hh[j][1] + acc_hl[j][1] + acc_lh[j][1] + ph1), pl0);
            pl1 = fmaf(vv0, tanh_fast(acc_hh[j][2] + acc_hl[j][2] + acc_lh[j][2] + ph0), pl1);
            pl1 = fmaf(vv1, tanh_fast(acc_hh[j][3] + acc_hl[j][3] + acc_lh[j][3] + ph1), pl1);
        }

        __syncthreads();   // all warps done with buffer (c&1) before refill
        if (tid == 0 && c + 2 < N_CHUNKS) {
            const int cn = c + 2;
            const uint32_t mbn = smem_u + SMBAR + 8 * (cn & 1);
            const uint32_t bhn = smem_u + SB + (cn & 1) * BUF_STRIDE;
            MBARRIER_EXPECT_TX(mbn, 2 * CH_BYTES);
            BULK_G2S(bhn,            g_w1t_hi + (size_t)cn * CH_BYTES, CH_BYTES, mbn);
            BULK_G2S(bhn + CH_BYTES, g_w1t_lo + (size_t)cn * CH_BYTES, CH_BYTES, mbn);
        }
    }

    // ---- reduce logit partials across the 4 lanes sharing a row ----
    pl0 += __shfl_xor_sync(0xffffffffu, pl0, 1);
    pl0 += __shfl_xor_sync(0xffffffffu, pl0, 2);
    pl1 += __shfl_xor_sync(0xffffffffu, pl1, 1);
    pl1 += __shfl_xor_sync(0xffffffffu, pl1, 2);
    if ((lane & 3) == 0) {
        w_s[m0 + (lane >> 2)]     = pl0;
        w_s[m0 + 8 + (lane >> 2)] = pl1;
    }
    __syncthreads();

    // ---- softmax per batch over L=64 (warps 0-3; bV shift-invariant) ----
    {
        const bool act = wid < 4;
        const int bb = (wid >> 1) & 1;
        const int li = (wid & 1) * 32 + lane;
        float lv = act ? w_s[bb * 64 + li] : -1e30f;
        float m = lv;
#pragma unroll
        for (int off = 16; off; off >>= 1)
            m = fmaxf(m, __shfl_xor_sync(0xffffffffu, m, off));
        if (act && lane == 0) red_s[wid] = m;
        __syncthreads();
        const float mx = fmaxf(red_s[bb * 2], red_s[bb * 2 + 1]);
        float e = act ? expf(lv - mx) : 0.f;
        float s = e;
#pragma unroll
        for (int off = 16; off; off >>= 1)
            s += __shfl_xor_sync(0xffffffffu, s, off);
        if (act && lane == 0) red_s[4 + wid] = s;
        __syncthreads();
        if (act) w_s[bb * 64 + li] = e / (red_s[4 + bb * 2] + red_s[5 + bb * 2]);
        __syncthreads();
    }

    // ---- context: ctx[bb,d] = sum_l w[bb,l] * (F_hi + F_lo)[bb*64+l, d] ----
    {
        const int d = tid;
#pragma unroll
        for (int bb = 0; bb < 2; ++bb) {
            float cacc = 0.f;
#pragma unroll 8
            for (int l = 0; l < 64; ++l) {
                const uint32_t off = (((uint32_t)(bb * 64 + l)) * PITCH + d) * 2;
                const float hi = __bfloat162float(*(const __nv_bfloat16*)(smem + SA_HI + off));
                const float lo = __bfloat162float(*(const __nv_bfloat16*)(smem + SA_LO + off));
                cacc = fmaf(w_s[bb * 64 + l], hi + lo, cacc);
            }
            if (ctx_out) ctx_out[(size_t)(b0 + bb) * D_SZ + d] = cacc;
        }
        if (w_out && tid < 128) w_out[(size_t)b0 * L_SZ + tid] = w_s[tid];
    }

    __syncthreads();
    if (tid == 0) {
        MBARRIER_INVAL(smem_u + SMBAR);
        MBARRIER_INVAL(smem_u + SMBAR + 8);
    }
}

// ---------------------------------------------------------------------------
extern "C" void kernel_launch(void* const* d_in, const int* in_sizes, int n_in,
                              void* d_out, int out_size)
{
    const float* features = (const float*)d_in[0];
    const float* hidden   = (const float*)d_in[1];
    const float* W1       = (const float*)d_in[2];
    const float* b1       = (const float*)d_in[3];
    const float* W2       = (const float*)d_in[4];
    const float* b2       = (const float*)d_in[5];
    const float* V        = (const float*)d_in[6];
    // d_in[7] = bV: softmax shift-invariant -> no output effect.

    float* out = (float*)d_out;
    float* ctx_out = nullptr;
    float* w_out   = nullptr;
    const int CTX_N = B_SZ * D_SZ;
    const int W_N   = B_SZ * L_SZ;
    if (out_size >= CTX_N + W_N) { ctx_out = out; w_out = out + CTX_N; }
    else if (out_size == CTX_N)  { ctx_out = out; }
    else if (out_size == W_N)    { w_out = out; }
    else                         { ctx_out = out; }

    prep_w1_kernel<<<D_SZ, U_SZ>>>(W1);

    dim3 g1(U_SZ / 64, B_SZ / 64);
    proj_h_kernel<<<g1, 256>>>(hidden, W2, b1, b2);

    cudaFuncSetAttribute(attn_mma_kernel,
                         cudaFuncAttributeMaxDynamicSharedMemorySize, SMEM_TOTAL);
    attn_mma_kernel<<<B_SZ / 2, 256, SMEM_TOTAL>>>(features, V, ctx_out, w_out);
}

// round 7
// speedup vs baseline: 1.1708x; 1.1708x over previous
#include <cuda_runtime.h>
#include <cuda_fp16.h>
#include <math.h>
#include <stdint.h>

#define B_SZ 2048
#define L_SZ 64
#define D_SZ 256
#define U_SZ 512

#define PITCH 264                     // fp16 elems per row (256 + 8 pad): conflict-free LDSM
#define CH_ROWS 32                    // u-rows per B chunk
#define N_CHUNKS 16                   // 512 / 32
#define CH_BYTES (CH_ROWS * PITCH * 2)   // 16896

// ---------------------------------------------------------------------------
// PTX helpers (base-PTX only; compiles under compute_103)
// ---------------------------------------------------------------------------
__device__ __forceinline__ uint32_t smem_to_u32(const void* p) {
    uint32_t a;
    asm("{ .reg .u64 t; cvta.to.shared.u64 t, %1; cvt.u32.u64 %0, t; }"
        : "=r"(a) : "l"(p));
    return a;
}

#define MBARRIER_INIT(mb, c) \
    asm volatile("mbarrier.init.shared.b64 [%0], %1;" \
                 :: "r"((uint32_t)(mb)), "r"((uint32_t)(c)) : "memory")
#define MBARRIER_INVAL(mb) \
    asm volatile("mbarrier.inval.shared.b64 [%0];" :: "r"((uint32_t)(mb)) : "memory")
#define MBARRIER_EXPECT_TX(mb, bytes) \
    asm volatile("mbarrier.arrive.expect_tx.shared.b64 _, [%0], %1;" \
                 :: "r"((uint32_t)(mb)), "r"((uint32_t)(bytes)) : "memory")

#define MBARRIER_WAIT_PARITY(mb, ph) do { \
    uint32_t _mb = (uint32_t)(mb); uint32_t _p = (uint32_t)(ph); uint32_t _done; \
    asm volatile("{\n\t.reg .pred p;\n\t" \
        "mbarrier.try_wait.parity.acquire.cta.shared::cta.b64 p, [%1], %2;\n\t" \
        "selp.b32 %0, 1, 0, p;\n\t}" : "=r"(_done) : "r"(_mb), "r"(_p) : "memory"); \
    if (!_done) { \
        asm volatile("{\n\t.reg .pred P1;\n\t" \
            "WL_%=:\n\t" \
            "mbarrier.try_wait.parity.acquire.cta.shared::cta.b64 P1, [%0], %1, 0x989680;\n\t" \
            "@P1 bra.uni WD_%=;\n\t" \
            "bra.uni WL_%=;\n\t" \
            "WD_%=:\n\t}" :: "r"(_mb), "r"(_p) : "memory"); \
    } \
} while (0)

// 1D bulk async copy gmem -> smem (TMA engine)
#define BULK_G2S(dst, src, sz, mb) \
    asm volatile("cp.async.bulk.shared::cluster.global.mbarrier::complete_tx::bytes " \
                 "[%0], [%1], %2, [%3];" \
                 :: "r"((uint32_t)(dst)), "l"(src), "r"((uint32_t)(sz)), \
                    "r"((uint32_t)(mb)) : "memory")

#define LDMX4(r0, r1, r2, r3, addr) \
    asm volatile("ldmatrix.sync.aligned.m8n8.x4.shared.b16 {%0,%1,%2,%3}, [%4];" \
                 : "=r"(r0), "=r"(r1), "=r"(r2), "=r"(r3) : "r"(addr))

// fp16 inputs, fp32 accumulate
#define MMA16816(c, a0, a1, a2, a3, b0, b1) \
    asm volatile("mma.sync.aligned.m16n8k16.row.col.f32.f16.f16.f32 " \
                 "{%0,%1,%2,%3},{%4,%5,%6,%7},{%8,%9},{%0,%1,%2,%3};" \
                 : "+f"((c)[0]), "+f"((c)[1]), "+f"((c)[2]), "+f"((c)[3]) \
                 : "r"(a0), "r"(a1), "r"(a2), "r"(a3), "r"(b0), "r"(b1))

__device__ __forceinline__ float tanh_fast(float x) {
    float e = __expf(2.f * x);
    return 1.f - __fdividef(2.f, e + 1.f);
}

// ---------------------------------------------------------------------------
// Device scratch (allocation-free)
// ---------------------------------------------------------------------------
__device__ float g_ph[B_SZ * U_SZ];
__device__ __align__(16) unsigned char g_w1t_hi[N_CHUNKS * CH_BYTES];
__device__ __align__(16) unsigned char g_w1t_lo[N_CHUNKS * CH_BYTES];

// ---------------------------------------------------------------------------
// Prep: W1[d][u] -> chunked W1^T (fp16 hi/lo), rows n=u%32, cols k=d, pitch 264
// ---------------------------------------------------------------------------
__global__ void prep_w1_kernel(const float* __restrict__ W1) {
    const int d = blockIdx.x;
    const int u = threadIdx.x;
    const float f = W1[(size_t)d * U_SZ + u];
    const __half hi = __float2half_rn(f);
    const __half lo = __float2half_rn(f - __half2float(hi));
    const int chunk = u >> 5, n = u & 31;
    const size_t off = (size_t)chunk * CH_BYTES + ((size_t)n * PITCH + d) * 2;
    *(__half*)(g_w1t_hi + off) = hi;
    *(__half*)(g_w1t_lo + off) = lo;
}

// ---------------------------------------------------------------------------
// proj_h: g_ph[b][u] = hidden[b,:].W2[:,u] + b1[u] + b2[u]
// ---------------------------------------------------------------------------
__global__ void proj_h_kernel(const float* __restrict__ hidden,
                              const float* __restrict__ W2,
                              const float* __restrict__ b1,
                              const float* __restrict__ b2)
{
    __shared__ float As[16][65];
    __shared__ float Bs[16][68];
    const int tid  = threadIdx.x;
    const int row0 = blockIdx.y * 64;
    const int col0 = blockIdx.x * 64;
    const int tr   = tid >> 4;
    const int tc   = tid & 15;

    float acc[4][4];
#pragma unroll
    for (int i = 0; i < 4; ++i)
#pragma unroll
        for (int j = 0; j < 4; ++j) acc[i][j] = 0.f;

    for (int k0 = 0; k0 < U_SZ; k0 += 16) {
#pragma unroll
        for (int t = 0; t < 4; ++t) {
            int idx = tid + 256 * t;
            As[idx & 15][idx >> 4] =
                hidden[(size_t)(row0 + (idx >> 4)) * U_SZ + k0 + (idx & 15)];
        }
#pragma unroll
        for (int t = 0; t < 4; ++t) {
            int idx = tid + 256 * t;
            Bs[idx >> 6][idx & 63] =
                W2[(size_t)(k0 + (idx >> 6)) * U_SZ + col0 + (idx & 63)];
        }
        __syncthreads();
#pragma unroll
        for (int k = 0; k < 16; ++k) {
            float a[4], bb[4];
#pragma unroll
            for (int i = 0; i < 4; ++i) a[i] = As[k][tr * 4 + i];
#pragma unroll
            for (int j = 0; j < 4; ++j) bb[j] = Bs[k][tc * 4 + j];
#pragma unroll
            for (int i = 0; i < 4; ++i)
#pragma unroll
                for (int j = 0; j < 4; ++j) acc[i][j] = fmaf(a[i], bb[j], acc[i][j]);
        }
        __syncthreads();
    }
#pragma unroll
    for (int i = 0; i < 4; ++i)
#pragma unroll
        for (int j = 0; j < 4; ++j) {
            int n = col0 + tc * 4 + j;
            g_ph[(size_t)(row0 + tr * 4 + i) * U_SZ + n] = acc[i][j] + b1[n] + b2[n];
        }
}

// ---------------------------------------------------------------------------
// Main fused kernel: 1 CTA = 2 batches (M=128 rows), 8 warps x 16 rows.
// fp16x2 scheme: A = fp16(features) single; W1 = fp16 hi + fp16 lo.
// D = A*Wh + A*Wl (2 HMMA products instead of 3).
// Context step reads fp32 features straight from gmem (L2-hot) -> no fp16
// error on the context path.
// SMEM byte offsets:
static constexpr int SA    = 0;                       // 67584 (A fp16)
static constexpr int SB    = 67584;                   // 2 bufs x (hi+lo) = 67584
static constexpr int BUF_STRIDE = 2 * CH_BYTES;       // 33792
static constexpr int SPH   = 135168;                  // 4096
static constexpr int SV    = 139264;                  // 2048
static constexpr int SW    = 141312;                  // 512
static constexpr int SRED  = 141824;                  // 64
static constexpr int SMBAR = 141888;                  // 2 x 8B
static constexpr int SMEM_TOTAL = 142080;
// ---------------------------------------------------------------------------
__global__ void __launch_bounds__(256, 1)
attn_mma_kernel(const float* __restrict__ features,
                const float* __restrict__ V,
                float* __restrict__ ctx_out,
                float* __restrict__ w_out)
{
    extern __shared__ __align__(1024) char smem[];
    const uint32_t smem_u = smem_to_u32(smem);
    const int tid  = threadIdx.x;
    const int wid  = tid >> 5;
    const int lane = tid & 31;
    const int b0   = blockIdx.x * 2;

    float* ph_s  = (float*)(smem + SPH);
    float* V_s   = (float*)(smem + SV);
    float* w_s   = (float*)(smem + SW);
    float* red_s = (float*)(smem + SRED);

    // ---- mbarriers + kick off first two B-chunk bulk copies ----
    if (tid == 0) {
        MBARRIER_INIT(smem_u + SMBAR, 1);
        MBARRIER_INIT(smem_u + SMBAR + 8, 1);
#pragma unroll
        for (int c = 0; c < 2; ++c) {
            const uint32_t mb = smem_u + SMBAR + 8 * c;
            const uint32_t bh = smem_u + SB + c * BUF_STRIDE;
            MBARRIER_EXPECT_TX(mb, 2 * CH_BYTES);
            BULK_G2S(bh,            g_w1t_hi + (size_t)c * CH_BYTES, CH_BYTES, mb);
            BULK_G2S(bh + CH_BYTES, g_w1t_lo + (size_t)c * CH_BYTES, CH_BYTES, mb);
        }
    }

    // ---- Stage features[b0..b0+1] as single fp16 (padded rows) ----
    {
        const float4* fsrc = (const float4*)(features + (size_t)b0 * L_SZ * D_SZ);
#pragma unroll 4
        for (int t = 0; t < 32; ++t) {
            const int idx = tid + 256 * t;
            const int row = idx >> 6;
            const int d   = (idx & 63) * 4;
            const float4 v = fsrc[idx];
            __half2 h0 = __float22half2_rn(make_float2(v.x, v.y));
            __half2 h1 = __float22half2_rn(make_float2(v.z, v.w));
            const uint32_t off = ((uint32_t)row * PITCH + d) * 2;
            *(uint2*)(smem + SA + off) =
                make_uint2(*(uint32_t*)&h0, *(uint32_t*)&h1);
        }
    }
#pragma unroll
    for (int t = 0; t < 4; ++t)
        ph_s[tid + 256 * t] = g_ph[(size_t)b0 * U_SZ + tid + 256 * t];
    V_s[tid]       = V[tid];
    V_s[tid + 256] = V[tid + 256];
    __syncthreads();

    // ---- ldmatrix address components ----
    const int m0 = wid * 16;
    const uint32_t a_row = (uint32_t)(m0 + (lane & 7) + ((lane >> 3) & 1) * 8);
    const uint32_t a_off = (a_row * PITCH + ((uint32_t)(lane >> 4)) * 8) * 2;
    const uint32_t b4_off = (((uint32_t)(lane & 7) + (((uint32_t)lane >> 4) & 1) * 8) * PITCH) * 2
                          + (((uint32_t)lane >> 3) & 1) * 16;
    const int phb = (wid >> 2) * U_SZ;

    // ---- Preload ALL A fragments into registers (single fp16: 64 regs) ----
    uint32_t ah[16][4];
#pragma unroll
    for (int kk = 0; kk < 16; ++kk) {
        const uint32_t koff = (uint32_t)kk * 32;
        LDMX4(ah[kk][0], ah[kk][1], ah[kk][2], ah[kk][3],
              smem_u + SA + a_off + koff);
    }

    float pl0 = 0.f, pl1 = 0.f;

    // ==================== chunk loop ====================
    for (int c = 0; c < N_CHUNKS; ++c) {
        const uint32_t mb = smem_u + SMBAR + 8 * (c & 1);
        MBARRIER_WAIT_PARITY(mb, (c >> 1) & 1);

        const uint32_t bh = smem_u + SB + (c & 1) * BUF_STRIDE;
        const uint32_t bl = bh + CH_BYTES;

        // Separate accumulators for the hi/lo products: 8 independent chains.
        float acc_hh[4][4], acc_hl[4][4];
#pragma unroll
        for (int j = 0; j < 4; ++j)
#pragma unroll
            for (int r = 0; r < 4; ++r) { acc_hh[j][r] = 0.f; acc_hl[j][r] = 0.f; }

#pragma unroll
        for (int kk = 0; kk < 16; ++kk) {
            const uint32_t koff = (uint32_t)kk * 32;
#pragma unroll
            for (int j2 = 0; j2 < 2; ++j2) {
                const uint32_t jb = b4_off + (uint32_t)j2 * (16 * PITCH * 2) + koff;
                uint32_t bh0, bh1, bh2, bh3, bl0, bl1, bl2, bl3;
                LDMX4(bh0, bh1, bh2, bh3, bh + jb);
                LDMX4(bl0, bl1, bl2, bl3, bl + jb);
                const int j = j2 * 2;
                MMA16816(acc_hh[j],     ah[kk][0], ah[kk][1], ah[kk][2], ah[kk][3], bh0, bh1);
                MMA16816(acc_hh[j + 1], ah[kk][0], ah[kk][1], ah[kk][2], ah[kk][3], bh2, bh3);
                MMA16816(acc_hl[j],     ah[kk][0], ah[kk][1], ah[kk][2], ah[kk][3], bl0, bl1);
                MMA16816(acc_hl[j + 1], ah[kk][0], ah[kk][1], ah[kk][2], ah[kk][3], bl2, bl3);
            }
        }

        // fused epilogue for this chunk's u-columns
#pragma unroll
        for (int j = 0; j < 4; ++j) {
            const int u = c * 32 + j * 8 + (lane & 3) * 2;
            const float ph0 = ph_s[phb + u],     vv0 = V_s[u];
            const float ph1 = ph_s[phb + u + 1], vv1 = V_s[u + 1];
            pl0 = fmaf(vv0, tanh_fast(acc_hh[j][0] + acc_hl[j][0] + ph0), pl0);
            pl0 = fmaf(vv1, tanh_fast(acc_hh[j][1] + acc_hl[j][1] + ph1), pl0);
            pl1 = fmaf(vv0, tanh_fast(acc_hh[j][2] + acc_hl[j][2] + ph0), pl1);
            pl1 = fmaf(vv1, tanh_fast(acc_hh[j][3] + acc_hl[j][3] + ph1), pl1);
        }

        __syncthreads();   // all warps done with buffer (c&1) before refill
        if (tid == 0 && c + 2 < N_CHUNKS) {
            const int cn = c + 2;
            const uint32_t mbn = smem_u + SMBAR + 8 * (cn & 1);
            const uint32_t bhn = smem_u + SB + (cn & 1) * BUF_STRIDE;
            MBARRIER_EXPECT_TX(mbn, 2 * CH_BYTES);
            BULK_G2S(bhn,            g_w1t_hi + (size_t)cn * CH_BYTES, CH_BYTES, mbn);
            BULK_G2S(bhn + CH_BYTES, g_w1t_lo + (size_t)cn * CH_BYTES, CH_BYTES, mbn);
        }
    }

    // ---- reduce logit partials across the 4 lanes sharing a row ----
    pl0 += __shfl_xor_sync(0xffffffffu, pl0, 1);
    pl0 += __shfl_xor_sync(0xffffffffu, pl0, 2);
    pl1 += __shfl_xor_sync(0xffffffffu, pl1, 1);
    pl1 += __shfl_xor_sync(0xffffffffu, pl1, 2);
    if ((lane & 3) == 0) {
        w_s[m0 + (lane >> 2)]     = pl0;
        w_s[m0 + 8 + (lane >> 2)] = pl1;
    }
    __syncthreads();

    // ---- softmax per batch over L=64 (warps 0-3; bV shift-invariant) ----
    {
        const bool act = wid < 4;
        const int bb = (wid >> 1) & 1;
        const int li = (wid & 1) * 32 + lane;
        float lv = act ? w_s[bb * 64 + li] : -1e30f;
        float m = lv;
#pragma unroll
        for (int off = 16; off; off >>= 1)
            m = fmaxf(m, __shfl_xor_sync(0xffffffffu, m, off));
        if (act && lane == 0) red_s[wid] = m;
        __syncthreads();
        const float mx = fmaxf(red_s[bb * 2], red_s[bb * 2 + 1]);
        float e = act ? expf(lv - mx) : 0.f;
        float s = e;
#pragma unroll
        for (int off = 16; off; off >>= 1)
            s += __shfl_xor_sync(0xffffffffu, s, off);
        if (act && lane == 0) red_s[4 + wid] = s;
        __syncthreads();
        if (act) w_s[bb * 64 + li] = e / (red_s[4 + bb * 2] + red_s[5 + bb * 2]);
        __syncthreads();
    }

    // ---- context from fp32 gmem features (L2-hot): no fp16 error here ----
    {
        const int d = tid;
#pragma unroll
        for (int bb = 0; bb < 2; ++bb) {
            const float* frow = features + (size_t)(b0 + bb) * L_SZ * D_SZ + d;
            float cacc = 0.f;
#pragma unroll 8
            for (int l = 0; l < 64; ++l)
                cacc = fmaf(w_s[bb * 64 + l], __ldg(frow + l * D_SZ), cacc);
            if (ctx_out) ctx_out[(size_t)(b0 + bb) * D_SZ + d] = cacc;
        }
        if (w_out && tid < 128) w_out[(size_t)b0 * L_SZ + tid] = w_s[tid];
    }

    __syncthreads();
    if (tid == 0) {
        MBARRIER_INVAL(smem_u + SMBAR);
        MBARRIER_INVAL(smem_u + SMBAR + 8);
    }
}

// ---------------------------------------------------------------------------
extern "C" void kernel_launch(void* const* d_in, const int* in_sizes, int n_in,
                              void* d_out, int out_size)
{
    const float* features = (const float*)d_in[0];
    const float* hidden   = (const float*)d_in[1];
    const float* W1       = (const float*)d_in[2];
    const float* b1       = (const float*)d_in[3];
    const float* W2       = (const float*)d_in[4];
    const float* b2       = (const float*)d_in[5];
    const float* V        = (const float*)d_in[6];
    // d_in[7] = bV: softmax shift-invariant -> no output effect.

    float* out = (float*)d_out;
    float* ctx_out = nullptr;
    float* w_out   = nullptr;
    const int CTX_N = B_SZ * D_SZ;
    const int W_N   = B_SZ * L_SZ;
    if (out_size >= CTX_N + W_N) { ctx_out = out; w_out = out + CTX_N; }
    else if (out_size == CTX_N)  { ctx_out = out; }
    else if (out_size == W_N)    { w_out = out; }
    else                         { ctx_out = out; }

    prep_w1_kernel<<<D_SZ, U_SZ>>>(W1);

    dim3 g1(U_SZ / 64, B_SZ / 64);
    proj_h_kernel<<<g1, 256>>>(hidden, W2, b1, b2);

    cudaFuncSetAttribute(attn_mma_kernel,
                         cudaFuncAttributeMaxDynamicSharedMemorySize, SMEM_TOTAL);
    attn_mma_kernel<<<B_SZ / 2, 256, SMEM_TOTAL>>>(features, V, ctx_out, w_out);
}

// round 8
// speedup vs baseline: 1.8386x; 1.5704x over previous
#include <cuda_runtime.h>
#include <cuda_fp16.h>
#include <math.h>
#include <stdint.h>

#define B_SZ 2048
#define L_SZ 64
#define D_SZ 256
#define U_SZ 512

#define PITCH 264                     // fp16 elems per row (256 + 8 pad): conflict-free LDSM
#define CH_ROWS 32                    // u-rows per B chunk
#define N_CHUNKS 16                   // 512 / 32
#define CH_BYTES (CH_ROWS * PITCH * 2)   // 16896

// ---------------------------------------------------------------------------
// PTX helpers (base-PTX only; compiles under compute_103)
// ---------------------------------------------------------------------------
__device__ __forceinline__ uint32_t smem_to_u32(const void* p) {
    uint32_t a;
    asm("{ .reg .u64 t; cvta.to.shared.u64 t, %1; cvt.u32.u64 %0, t; }"
        : "=r"(a) : "l"(p));
    return a;
}

#define MBARRIER_INIT(mb, c) \
    asm volatile("mbarrier.init.shared.b64 [%0], %1;" \
                 :: "r"((uint32_t)(mb)), "r"((uint32_t)(c)) : "memory")
#define MBARRIER_INVAL(mb) \
    asm volatile("mbarrier.inval.shared.b64 [%0];" :: "r"((uint32_t)(mb)) : "memory")
#define MBARRIER_EXPECT_TX(mb, bytes) \
    asm volatile("mbarrier.arrive.expect_tx.shared.b64 _, [%0], %1;" \
                 :: "r"((uint32_t)(mb)), "r"((uint32_t)(bytes)) : "memory")

#define MBARRIER_WAIT_PARITY(mb, ph) do { \
    uint32_t _mb = (uint32_t)(mb); uint32_t _p = (uint32_t)(ph); uint32_t _done; \
    asm volatile("{\n\t.reg .pred p;\n\t" \
        "mbarrier.try_wait.parity.acquire.cta.shared::cta.b64 p, [%1], %2;\n\t" \
        "selp.b32 %0, 1, 0, p;\n\t}" : "=r"(_done) : "r"(_mb), "r"(_p) : "memory"); \
    if (!_done) { \
        asm volatile("{\n\t.reg .pred P1;\n\t" \
            "WL_%=:\n\t" \
            "mbarrier.try_wait.parity.acquire.cta.shared::cta.b64 P1, [%0], %1, 0x989680;\n\t" \
            "@P1 bra.uni WD_%=;\n\t" \
            "bra.uni WL_%=;\n\t" \
            "WD_%=:\n\t}" :: "r"(_mb), "r"(_p) : "memory"); \
    } \
} while (0)

// 1D bulk async copy gmem -> smem (TMA engine)
#define BULK_G2S(dst, src, sz, mb) \
    asm volatile("cp.async.bulk.shared::cluster.global.mbarrier::complete_tx::bytes " \
                 "[%0], [%1], %2, [%3];" \
                 :: "r"((uint32_t)(dst)), "l"(src), "r"((uint32_t)(sz)), \
                    "r"((uint32_t)(mb)) : "memory")

#define LDMX4(r0, r1, r2, r3, addr) \
    asm volatile("ldmatrix.sync.aligned.m8n8.x4.shared.b16 {%0,%1,%2,%3}, [%4];" \
                 : "=r"(r0), "=r"(r1), "=r"(r2), "=r"(r3) : "r"(addr))

// fp16 inputs, fp32 accumulate
#define MMA16816(c, a0, a1, a2, a3, b0, b1) \
    asm volatile("mma.sync.aligned.m16n8k16.row.col.f32.f16.f16.f32 " \
                 "{%0,%1,%2,%3},{%4,%5,%6,%7},{%8,%9},{%0,%1,%2,%3};" \
                 : "+f"((c)[0]), "+f"((c)[1]), "+f"((c)[2]), "+f"((c)[3]) \
                 : "r"(a0), "r"(a1), "r"(a2), "r"(a3), "r"(b0), "r"(b1))

__device__ __forceinline__ float tanh_fast(float x) {
    float e = __expf(2.f * x);
    return 1.f - __fdividef(2.f, e + 1.f);
}

// ---------------------------------------------------------------------------
// Device scratch (allocation-free)
// ---------------------------------------------------------------------------
__device__ float g_ph[B_SZ * U_SZ];
__device__ __align__(16) unsigned char g_w1t[N_CHUNKS * CH_BYTES];

// ---------------------------------------------------------------------------
// Prep: W1[d][u] -> chunked W1^T (single fp16), rows n=u%32, cols k=d, pitch 264
// ---------------------------------------------------------------------------
__global__ void prep_w1_kernel(const float* __restrict__ W1) {
    const int d = blockIdx.x;
    const int u = threadIdx.x;
    const float f = W1[(size_t)d * U_SZ + u];
    const int chunk = u >> 5, n = u & 31;
    const size_t off = (size_t)chunk * CH_BYTES + ((size_t)n * PITCH + d) * 2;
    *(__half*)(g_w1t + off) = __float2half_rn(f);
}

// ---------------------------------------------------------------------------
// proj_h: g_ph[b][u] = hidden[b,:].W2[:,u] + b1[u] + b2[u]
// ---------------------------------------------------------------------------
__global__ void proj_h_kernel(const float* __restrict__ hidden,
                              const float* __restrict__ W2,
                              const float* __restrict__ b1,
                              const float* __restrict__ b2)
{
    __shared__ float As[16][65];
    __shared__ float Bs[16][68];
    const int tid  = threadIdx.x;
    const int row0 = blockIdx.y * 64;
    const int col0 = blockIdx.x * 64;
    const int tr   = tid >> 4;
    const int tc   = tid & 15;

    float acc[4][4];
#pragma unroll
    for (int i = 0; i < 4; ++i)
#pragma unroll
        for (int j = 0; j < 4; ++j) acc[i][j] = 0.f;

    for (int k0 = 0; k0 < U_SZ; k0 += 16) {
#pragma unroll
        for (int t = 0; t < 4; ++t) {
            int idx = tid + 256 * t;
            As[idx & 15][idx >> 4] =
                hidden[(size_t)(row0 + (idx >> 4)) * U_SZ + k0 + (idx & 15)];
        }
#pragma unroll
        for (int t = 0; t < 4; ++t) {
            int idx = tid + 256 * t;
            Bs[idx >> 6][idx & 63] =
                W2[(size_t)(k0 + (idx >> 6)) * U_SZ + col0 + (idx & 63)];
        }
        __syncthreads();
#pragma unroll
        for (int k = 0; k < 16; ++k) {
            float a[4], bb[4];
#pragma unroll
            for (int i = 0; i < 4; ++i) a[i] = As[k][tr * 4 + i];
#pragma unroll
            for (int j = 0; j < 4; ++j) bb[j] = Bs[k][tc * 4 + j];
#pragma unroll
            for (int i = 0; i < 4; ++i)
#pragma unroll
                for (int j = 0; j < 4; ++j) acc[i][j] = fmaf(a[i], bb[j], acc[i][j]);
        }
        __syncthreads();
    }
#pragma unroll
    for (int i = 0; i < 4; ++i)
#pragma unroll
        for (int j = 0; j < 4; ++j) {
            int n = col0 + tc * 4 + j;
            g_ph[(size_t)(row0 + tr * 4 + i) * U_SZ + n] = acc[i][j] + b1[n] + b2[n];
        }
}

// ---------------------------------------------------------------------------
// Main fused kernel: 1 CTA = 2 batches (M=128 rows), 8 warps x 16 rows.
// Single fp16 x fp16 MMA product (A and W both RN-rounded fp16; err ~2e-4).
// Context step reads fp32 features from gmem (L2-hot) -> exact.
// SMEM fits 2 CTAs/SM (~106 KB each); regs ~115 -> occupancy 2.
// SMEM byte offsets:
static constexpr int SA    = 0;                       // 67584 (A fp16)
static constexpr int SB    = 67584;                   // 2 bufs x 16896 = 33792
static constexpr int BUF_STRIDE = CH_BYTES;           // 16896
static constexpr int SPH   = 101376;                  // 4096
static constexpr int SV    = 105472;                  // 2048
static constexpr int SW    = 107520;                  // 512
static constexpr int SRED  = 108032;                  // 64
static constexpr int SMBAR = 108096;                  // 2 x 8B
static constexpr int SMEM_TOTAL = 108160;
// ---------------------------------------------------------------------------
__global__ void __launch_bounds__(256, 2)
attn_mma_kernel(const float* __restrict__ features,
                const float* __restrict__ V,
                float* __restrict__ ctx_out,
                float* __restrict__ w_out)
{
    extern __shared__ __align__(1024) char smem[];
    const uint32_t smem_u = smem_to_u32(smem);
    const int tid  = threadIdx.x;
    const int wid  = tid >> 5;
    const int lane = tid & 31;
    const int b0   = blockIdx.x * 2;

    float* ph_s  = (float*)(smem + SPH);
    float* V_s   = (float*)(smem + SV);
    float* w_s   = (float*)(smem + SW);
    float* red_s = (float*)(smem + SRED);

    // ---- mbarriers + kick off first two B-chunk bulk copies ----
    if (tid == 0) {
        MBARRIER_INIT(smem_u + SMBAR, 1);
        MBARRIER_INIT(smem_u + SMBAR + 8, 1);
#pragma unroll
        for (int c = 0; c < 2; ++c) {
            const uint32_t mb = smem_u + SMBAR + 8 * c;
            MBARRIER_EXPECT_TX(mb, CH_BYTES);
            BULK_G2S(smem_u + SB + c * BUF_STRIDE,
                     g_w1t + (size_t)c * CH_BYTES, CH_BYTES, mb);
        }
    }

    // ---- Stage features[b0..b0+1] as single fp16 (padded rows) ----
    {
        const float4* fsrc = (const float4*)(features + (size_t)b0 * L_SZ * D_SZ);
#pragma unroll 4
        for (int t = 0; t < 32; ++t) {
            const int idx = tid + 256 * t;
            const int row = idx >> 6;
            const int d   = (idx & 63) * 4;
            const float4 v = fsrc[idx];
            __half2 h0 = __float22half2_rn(make_float2(v.x, v.y));
            __half2 h1 = __float22half2_rn(make_float2(v.z, v.w));
            const uint32_t off = ((uint32_t)row * PITCH + d) * 2;
            *(uint2*)(smem + SA + off) =
                make_uint2(*(uint32_t*)&h0, *(uint32_t*)&h1);
        }
    }
#pragma unroll
    for (int t = 0; t < 4; ++t)
        ph_s[tid + 256 * t] = g_ph[(size_t)b0 * U_SZ + tid + 256 * t];
    V_s[tid]       = V[tid];
    V_s[tid + 256] = V[tid + 256];
    __syncthreads();

    // ---- ldmatrix address components ----
    const int m0 = wid * 16;
    const uint32_t a_row = (uint32_t)(m0 + (lane & 7) + ((lane >> 3) & 1) * 8);
    const uint32_t a_off = (a_row * PITCH + ((uint32_t)(lane >> 4)) * 8) * 2;
    const uint32_t b4_off = (((uint32_t)(lane & 7) + (((uint32_t)lane >> 4) & 1) * 8) * PITCH) * 2
                          + (((uint32_t)lane >> 3) & 1) * 16;
    const int phb = (wid >> 2) * U_SZ;

    // ---- Preload ALL A fragments into registers (64 regs) ----
    uint32_t ah[16][4];
#pragma unroll
    for (int kk = 0; kk < 16; ++kk) {
        const uint32_t koff = (uint32_t)kk * 32;
        LDMX4(ah[kk][0], ah[kk][1], ah[kk][2], ah[kk][3],
              smem_u + SA + a_off + koff);
    }

    float pl0 = 0.f, pl1 = 0.f;

    // ==================== chunk loop ====================
    for (int c = 0; c < N_CHUNKS; ++c) {
        const uint32_t mb = smem_u + SMBAR + 8 * (c & 1);
        MBARRIER_WAIT_PARITY(mb, (c >> 1) & 1);

        const uint32_t bbase = smem_u + SB + (c & 1) * BUF_STRIDE;

        float acc[4][4];
#pragma unroll
        for (int j = 0; j < 4; ++j)
#pragma unroll
            for (int r = 0; r < 4; ++r) acc[j][r] = 0.f;

#pragma unroll
        for (int kk = 0; kk < 16; ++kk) {
            const uint32_t koff = (uint32_t)kk * 32;
#pragma unroll
            for (int j2 = 0; j2 < 2; ++j2) {
                const uint32_t jb = b4_off + (uint32_t)j2 * (16 * PITCH * 2) + koff;
                uint32_t b0r, b1r, b2r, b3r;
                LDMX4(b0r, b1r, b2r, b3r, bbase + jb);
                const int j = j2 * 2;
                MMA16816(acc[j],     ah[kk][0], ah[kk][1], ah[kk][2], ah[kk][3], b0r, b1r);
                MMA16816(acc[j + 1], ah[kk][0], ah[kk][1], ah[kk][2], ah[kk][3], b2r, b3r);
            }
        }

        // fused epilogue for this chunk's u-columns
#pragma unroll
        for (int j = 0; j < 4; ++j) {
            const int u = c * 32 + j * 8 + (lane & 3) * 2;
            const float ph0 = ph_s[phb + u],     vv0 = V_s[u];
            const float ph1 = ph_s[phb + u + 1], vv1 = V_s[u + 1];
            pl0 = fmaf(vv0, tanh_fast(acc[j][0] + ph0), pl0);
            pl0 = fmaf(vv1, tanh_fast(acc[j][1] + ph1), pl0);
            pl1 = fmaf(vv0, tanh_fast(acc[j][2] + ph0), pl1);
            pl1 = fmaf(vv1, tanh_fast(acc[j][3] + ph1), pl1);
        }

        __syncthreads();   // all warps done with buffer (c&1) before refill
        if (tid == 0 && c + 2 < N_CHUNKS) {
            const int cn = c + 2;
            const uint32_t mbn = smem_u + SMBAR + 8 * (cn & 1);
            MBARRIER_EXPECT_TX(mbn, CH_BYTES);
            BULK_G2S(smem_u + SB + (cn & 1) * BUF_STRIDE,
                     g_w1t + (size_t)cn * CH_BYTES, CH_BYTES, mbn);
        }
    }

    // ---- reduce logit partials across the 4 lanes sharing a row ----
    pl0 += __shfl_xor_sync(0xffffffffu, pl0, 1);
    pl0 += __shfl_xor_sync(0xffffffffu, pl0, 2);
    pl1 += __shfl_xor_sync(0xffffffffu, pl1, 1);
    pl1 += __shfl_xor_sync(0xffffffffu, pl1, 2);
    if ((lane & 3) == 0) {
        w_s[m0 + (lane >> 2)]     = pl0;
        w_s[m0 + 8 + (lane >> 2)] = pl1;
    }
    __syncthreads();

    // ---- softmax per batch over L=64 (warps 0-3; bV shift-invariant) ----
    {
        const bool act = wid < 4;
        const int bb = (wid >> 1) & 1;
        const int li = (wid & 1) * 32 + lane;
        float lv = act ? w_s[bb * 64 + li] : -1e30f;
        float m = lv;
#pragma unroll
        for (int off = 16; off; off >>= 1)
            m = fmaxf(m, __shfl_xor_sync(0xffffffffu, m, off));
        if (act && lane == 0) red_s[wid] = m;
        __syncthreads();
        const float mx = fmaxf(red_s[bb * 2], red_s[bb * 2 + 1]);
        float e = act ? expf(lv - mx) : 0.f;
        float s = e;
#pragma unroll
        for (int off = 16; off; off >>= 1)
            s += __shfl_xor_sync(0xffffffffu, s, off);
        if (act && lane == 0) red_s[4 + wid] = s;
        __syncthreads();
        if (act) w_s[bb * 64 + li] = e / (red_s[4 + bb * 2] + red_s[5 + bb * 2]);
        __syncthreads();
    }

    // ---- context from fp32 gmem features (L2-hot): exact path ----
    {
        const int d = tid;
#pragma unroll
        for (int bb = 0; bb < 2; ++bb) {
            const float* frow = features + (size_t)(b0 + bb) * L_SZ * D_SZ + d;
            float cacc = 0.f;
#pragma unroll 8
            for (int l = 0; l < 64; ++l)
                cacc = fmaf(w_s[bb * 64 + l], __ldg(frow + l * D_SZ), cacc);
            if (ctx_out) ctx_out[(size_t)(b0 + bb) * D_SZ + d] = cacc;
        }
        if (w_out && tid < 128) w_out[(size_t)b0 * L_SZ + tid] = w_s[tid];
    }

    __syncthreads();
    if (tid == 0) {
        MBARRIER_INVAL(smem_u + SMBAR);
        MBARRIER_INVAL(smem_u + SMBAR + 8);
    }
}

// ---------------------------------------------------------------------------
extern "C" void kernel_launch(void* const* d_in, const int* in_sizes, int n_in,
                              void* d_out, int out_size)
{
    const float* features = (const float*)d_in[0];
    const float* hidden   = (const float*)d_in[1];
    const float* W1       = (const float*)d_in[2];
    const float* b1       = (const float*)d_in[3];
    const float* W2       = (const float*)d_in[4];
    const float* b2       = (const float*)d_in[5];
    const float* V        = (const float*)d_in[6];
    // d_in[7] = bV: softmax shift-invariant -> no output effect.

    float* out = (float*)d_out;
    float* ctx_out = nullptr;
    float* w_out   = nullptr;
    const int CTX_N = B_SZ * D_SZ;
    const int W_N   = B_SZ * L_SZ;
    if (out_size >= CTX_N + W_N) { ctx_out = out; w_out = out + CTX_N; }
    else if (out_size == CTX_N)  { ctx_out = out; }
    else if (out_size == W_N)    { w_out = out; }
    else                         { ctx_out = out; }

    prep_w1_kernel<<<D_SZ, U_SZ>>>(W1);

    dim3 g1(U_SZ / 64, B_SZ / 64);
    proj_h_kernel<<<g1, 256>>>(hidden, W2, b1, b2);

    cudaFuncSetAttribute(attn_mma_kernel,
                         cudaFuncAttributeMaxDynamicSharedMemorySize, SMEM_TOTAL);
    attn_mma_kernel<<<B_SZ / 2, 256, SMEM_TOTAL>>>(features, V, ctx_out, w_out);
}

// round 9
// speedup vs baseline: 2.5387x; 1.3808x over previous
#include <cuda_runtime.h>
#include <cuda_fp16.h>
#include <math.h>
#include <stdint.h>

#define B_SZ 2048
#define L_SZ 64
#define D_SZ 256
#define U_SZ 512

// ---- attn tiling ----
#define PITCH 264                        // fp16 elems/row (256+8): conflict-free LDSM
#define CH_ROWS 32
#define N_CHUNKS 16
#define CH_BYTES (CH_ROWS * PITCH * 2)   // 16896

// ---- proj tiling (K = 512) ----
#define PITCH2 520                       // 512+8
#define CH2_BYTES (32 * PITCH2 * 2)      // 33280
#define A2_BYTES (128 * PITCH2 * 2)      // 133120

// ---------------------------------------------------------------------------
// PTX helpers (base-PTX only; compiles under compute_103)
// ---------------------------------------------------------------------------
__device__ __forceinline__ uint32_t smem_to_u32(const void* p) {
    uint32_t a;
    asm("{ .reg .u64 t; cvta.to.shared.u64 t, %1; cvt.u32.u64 %0, t; }"
        : "=r"(a) : "l"(p));
    return a;
}

#define MBARRIER_INIT(mb, c) \
    asm volatile("mbarrier.init.shared.b64 [%0], %1;" \
                 :: "r"((uint32_t)(mb)), "r"((uint32_t)(c)) : "memory")
#define MBARRIER_INVAL(mb) \
    asm volatile("mbarrier.inval.shared.b64 [%0];" :: "r"((uint32_t)(mb)) : "memory")
#define MBARRIER_EXPECT_TX(mb, bytes) \
    asm volatile("mbarrier.arrive.expect_tx.shared.b64 _, [%0], %1;" \
                 :: "r"((uint32_t)(mb)), "r"((uint32_t)(bytes)) : "memory")
#define MBARRIER_ARRIVE(mb) \
    asm volatile("mbarrier.arrive.shared.b64 _, [%0];" \
                 :: "r"((uint32_t)(mb)) : "memory")

#define MBARRIER_WAIT_PARITY(mb, ph) do { \
    uint32_t _mb = (uint32_t)(mb); uint32_t _p = (uint32_t)(ph); uint32_t _done; \
    asm volatile("{\n\t.reg .pred p;\n\t" \
        "mbarrier.try_wait.parity.acquire.cta.shared::cta.b64 p, [%1], %2;\n\t" \
        "selp.b32 %0, 1, 0, p;\n\t}" : "=r"(_done) : "r"(_mb), "r"(_p) : "memory"); \
    if (!_done) { \
        asm volatile("{\n\t.reg .pred P1;\n\t" \
            "WL_%=:\n\t" \
            "mbarrier.try_wait.parity.acquire.cta.shared::cta.b64 P1, [%0], %1, 0x989680;\n\t" \
            "@P1 bra.uni WD_%=;\n\t" \
            "bra.uni WL_%=;\n\t" \
            "WD_%=:\n\t}" :: "r"(_mb), "r"(_p) : "memory"); \
    } \
} while (0)

#define BULK_G2S(dst, src, sz, mb) \
    asm volatile("cp.async.bulk.shared::cluster.global.mbarrier::complete_tx::bytes " \
                 "[%0], [%1], %2, [%3];" \
                 :: "r"((uint32_t)(dst)), "l"(src), "r"((uint32_t)(sz)), \
                    "r"((uint32_t)(mb)) : "memory")

#define LDMX4(r0, r1, r2, r3, addr) \
    asm volatile("ldmatrix.sync.aligned.m8n8.x4.shared.b16 {%0,%1,%2,%3}, [%4];" \
                 : "=r"(r0), "=r"(r1), "=r"(r2), "=r"(r3) : "r"(addr))

#define MMA16816(c, a0, a1, a2, a3, b0, b1) \
    asm volatile("mma.sync.aligned.m16n8k16.row.col.f32.f16.f16.f32 " \
                 "{%0,%1,%2,%3},{%4,%5,%6,%7},{%8,%9},{%0,%1,%2,%3};" \
                 : "+f"((c)[0]), "+f"((c)[1]), "+f"((c)[2]), "+f"((c)[3]) \
                 : "r"(a0), "r"(a1), "r"(a2), "r"(a3), "r"(b0), "r"(b1))

__device__ __forceinline__ float tanh_fast(float x) {
    float e = __expf(2.f * x);
    return 1.f - __fdividef(2.f, e + 1.f);
}

// ---------------------------------------------------------------------------
// Device scratch (allocation-free)
// ---------------------------------------------------------------------------
__device__ float g_ph[B_SZ * U_SZ];
__device__ __align__(16) unsigned char g_w1t[N_CHUNKS * CH_BYTES];       // W1^T fp16 chunks
__device__ __align__(16) unsigned char g_w2t[16 * CH2_BYTES];            // W2^T fp16 chunks
__device__ __align__(16) unsigned char g_h16[B_SZ * PITCH2 * 2];         // hidden fp16 pitched

// ---------------------------------------------------------------------------
// Combined prep: hidden->fp16 (pitch 520), W1^T chunks (pitch 264),
//                W2^T chunks (pitch 520). One launch.
// ---------------------------------------------------------------------------
__global__ void prep_all_kernel(const float* __restrict__ hidden,
                                const float* __restrict__ W1,
                                const float* __restrict__ W2)
{
    const int bid = blockIdx.x;
    const int tid = threadIdx.x;
    if (bid < B_SZ) {                                  // hidden row b
        const int b = bid;
#pragma unroll
        for (int h = 0; h < 2; ++h) {
            const int k = tid + h * 256;
            *(__half*)(g_h16 + ((size_t)b * PITCH2 + k) * 2) =
                __float2half_rn(hidden[(size_t)b * U_SZ + k]);
        }
    } else if (bid < B_SZ + D_SZ) {                    // W1 row d
        const int d = bid - B_SZ;
#pragma unroll
        for (int h = 0; h < 2; ++h) {
            const int u = tid + h * 256;
            const int chunk = u >> 5, n = u & 31;
            *(__half*)(g_w1t + (size_t)chunk * CH_BYTES + ((size_t)n * PITCH + d) * 2) =
                __float2half_rn(W1[(size_t)d * U_SZ + u]);
        }
    } else {                                           // W2 row k (u_in)
        const int k = bid - B_SZ - D_SZ;
#pragma unroll
        for (int h = 0; h < 2; ++h) {
            const int n = tid + h * 256;               // u_out
            const int chunk = n >> 5, nn = n & 31;
            *(__half*)(g_w2t + (size_t)chunk * CH2_BYTES + ((size_t)nn * PITCH2 + k) * 2) =
                __float2half_rn(W2[(size_t)k * U_SZ + n]);
        }
    }
}

// ---------------------------------------------------------------------------
// proj via tensor cores: g_ph[m][u] = hidden[m,:].W2[:,u] + b1[u] + b2[u]
// grid = 16 mq x 8 nq = 128 CTAs. M=128 rows, N=64 cols, K=512 per CTA.
// SMEM: A (133120) | B 2 chunks (66560) | bias (256) | mbars
static constexpr int P_SA    = 0;
static constexpr int P_SB    = A2_BYTES;               // 133120
static constexpr int P_SBIAS = P_SB + 2 * CH2_BYTES;   // 199680
static constexpr int P_SMBAR = P_SBIAS + 256;          // 199936
static constexpr int P_SMEM  = P_SMBAR + 64;           // 200000
// ---------------------------------------------------------------------------
__global__ void __launch_bounds__(256, 1)
proj_mma_kernel(const float* __restrict__ b1, const float* __restrict__ b2)
{
    extern __shared__ __align__(1024) char smem[];
    const uint32_t smem_u = smem_to_u32(smem);
    const int tid  = threadIdx.x;
    const int wid  = tid >> 5;
    const int lane = tid & 31;
    const int mq   = blockIdx.x >> 3;
    const int nq   = blockIdx.x & 7;

    float* sbias = (float*)(smem + P_SBIAS);

    if (tid == 0) {
        MBARRIER_INIT(smem_u + P_SMBAR, 1);            // A full
        MBARRIER_INIT(smem_u + P_SMBAR + 8, 1);        // B0 full
        MBARRIER_INIT(smem_u + P_SMBAR + 16, 1);       // B1 full
        MBARRIER_EXPECT_TX(smem_u + P_SMBAR, A2_BYTES);
        BULK_G2S(smem_u + P_SA, g_h16 + (size_t)mq * A2_BYTES, A2_BYTES,
                 smem_u + P_SMBAR);
#pragma unroll
        for (int c = 0; c < 2; ++c) {
            MBARRIER_EXPECT_TX(smem_u + P_SMBAR + 8 + 8 * c, CH2_BYTES);
            BULK_G2S(smem_u + P_SB + c * CH2_BYTES,
                     g_w2t + (size_t)(nq * 2 + c) * CH2_BYTES, CH2_BYTES,
                     smem_u + P_SMBAR + 8 + 8 * c);
        }
    }
    if (tid < 64) sbias[tid] = b1[nq * 64 + tid] + b2[nq * 64 + tid];
    __syncthreads();

    MBARRIER_WAIT_PARITY(smem_u + P_SMBAR, 0);         // A ready

    // ldmatrix addressing (pitch 520)
    const uint32_t a_row = (uint32_t)(wid * 16 + (lane & 7) + ((lane >> 3) & 1) * 8);
    const uint32_t a_off = (a_row * PITCH2 + ((uint32_t)(lane >> 4)) * 8) * 2;
    const uint32_t b4_off = (((uint32_t)(lane & 7) + (((uint32_t)lane >> 4) & 1) * 8) * PITCH2) * 2
                          + (((uint32_t)lane >> 3) & 1) * 16;

    // preload all A fragments (K=512 -> 32 kk steps, 128 regs)
    uint32_t ah[32][4];
#pragma unroll
    for (int kk = 0; kk < 32; ++kk)
        LDMX4(ah[kk][0], ah[kk][1], ah[kk][2], ah[kk][3],
              smem_u + P_SA + a_off + (uint32_t)kk * 32);

#pragma unroll
    for (int c = 0; c < 2; ++c) {
        MBARRIER_WAIT_PARITY(smem_u + P_SMBAR + 8 + 8 * c, 0);
        const uint32_t bbase = smem_u + P_SB + c * CH2_BYTES;

        float acc[4][4];
#pragma unroll
        for (int j = 0; j < 4; ++j)
#pragma unroll
            for (int r = 0; r < 4; ++r) acc[j][r] = 0.f;

#pragma unroll
        for (int kk = 0; kk < 32; ++kk) {
            const uint32_t koff = (uint32_t)kk * 32;
#pragma unroll
            for (int j2 = 0; j2 < 2; ++j2) {
                uint32_t b0r, b1r, b2r, b3r;
                LDMX4(b0r, b1r, b2r, b3r,
                      bbase + b4_off + (uint32_t)j2 * (16 * PITCH2 * 2) + koff);
                const int j = j2 * 2;
                MMA16816(acc[j],     ah[kk][0], ah[kk][1], ah[kk][2], ah[kk][3], b0r, b1r);
                MMA16816(acc[j + 1], ah[kk][0], ah[kk][1], ah[kk][2], ah[kk][3], b2r, b3r);
            }
        }

#pragma unroll
        for (int j = 0; j < 4; ++j) {
            const int ul = c * 32 + j * 8 + (lane & 3) * 2;
            const int ug = nq * 64 + ul;
            const int m  = mq * 128 + wid * 16 + (lane >> 2);
            float2 v0 = make_float2(acc[j][0] + sbias[ul], acc[j][1] + sbias[ul + 1]);
            float2 v1 = make_float2(acc[j][2] + sbias[ul], acc[j][3] + sbias[ul + 1]);
            *(float2*)&g_ph[(size_t)m * U_SZ + ug]       = v0;
            *(float2*)&g_ph[(size_t)(m + 8) * U_SZ + ug] = v1;
        }
    }

    __syncthreads();
    if (tid == 0) {
        MBARRIER_INVAL(smem_u + P_SMBAR);
        MBARRIER_INVAL(smem_u + P_SMBAR + 8);
        MBARRIER_INVAL(smem_u + P_SMBAR + 16);
    }
}

// ---------------------------------------------------------------------------
// Main fused attention: 1 CTA = 2 batches (M=128), 8 warps x 16 rows.
// Per-chunk __syncthreads replaced by 8-arrival "empty" mbarriers:
// only the producer thread (tid 0) ever waits on buffer emptiness.
static constexpr int SA    = 0;                       // 67584 (A fp16)
static constexpr int SB    = 67584;                   // 2 bufs x 16896
static constexpr int BUF_STRIDE = CH_BYTES;
static constexpr int SPH   = 101376;                  // 4096
static constexpr int SV    = 105472;                  // 2048
static constexpr int SW    = 107520;                  // 512
static constexpr int SRED  = 108032;                  // 64
static constexpr int SMBAR = 108096;                  // full[2] + empty[2]
static constexpr int SMEM_TOTAL = 108160;
// ---------------------------------------------------------------------------
__global__ void __launch_bounds__(256, 2)
attn_mma_kernel(const float* __restrict__ features,
                const float* __restrict__ V,
                float* __restrict__ ctx_out,
                float* __restrict__ w_out)
{
    extern __shared__ __align__(1024) char smem[];
    const uint32_t smem_u = smem_to_u32(smem);
    const int tid  = threadIdx.x;
    const int wid  = tid >> 5;
    const int lane = tid & 31;
    const int b0   = blockIdx.x * 2;

    float* ph_s  = (float*)(smem + SPH);
    float* V_s   = (float*)(smem + SV);
    float* w_s   = (float*)(smem + SW);
    float* red_s = (float*)(smem + SRED);

    if (tid == 0) {
        MBARRIER_INIT(smem_u + SMBAR, 1);          // full 0
        MBARRIER_INIT(smem_u + SMBAR + 8, 1);      // full 1
        MBARRIER_INIT(smem_u + SMBAR + 16, 8);     // empty 0 (8 warps)
        MBARRIER_INIT(smem_u + SMBAR + 24, 8);     // empty 1
#pragma unroll
        for (int c = 0; c < 2; ++c) {
            const uint32_t mb = smem_u + SMBAR + 8 * c;
            MBARRIER_EXPECT_TX(mb, CH_BYTES);
            BULK_G2S(smem_u + SB + c * BUF_STRIDE,
                     g_w1t + (size_t)c * CH_BYTES, CH_BYTES, mb);
        }
    }

    // ---- Stage features[b0..b0+1] as fp16 (padded rows) ----
    {
        const float4* fsrc = (const float4*)(features + (size_t)b0 * L_SZ * D_SZ);
#pragma unroll 4
        for (int t = 0; t < 32; ++t) {
            const int idx = tid + 256 * t;
            const int row = idx >> 6;
            const int d   = (idx & 63) * 4;
            const float4 v = fsrc[idx];
            __half2 h0 = __float22half2_rn(make_float2(v.x, v.y));
            __half2 h1 = __float22half2_rn(make_float2(v.z, v.w));
            const uint32_t off = ((uint32_t)row * PITCH + d) * 2;
            *(uint2*)(smem + SA + off) =
                make_uint2(*(uint32_t*)&h0, *(uint32_t*)&h1);
        }
    }
#pragma unroll
    for (int t = 0; t < 4; ++t)
        ph_s[tid + 256 * t] = g_ph[(size_t)b0 * U_SZ + tid + 256 * t];
    V_s[tid]       = V[tid];
    V_s[tid + 256] = V[tid + 256];
    __syncthreads();

    const int m0 = wid * 16;
    const uint32_t a_row = (uint32_t)(m0 + (lane & 7) + ((lane >> 3) & 1) * 8);
    const uint32_t a_off = (a_row * PITCH + ((uint32_t)(lane >> 4)) * 8) * 2;
    const uint32_t b4_off = (((uint32_t)(lane & 7) + (((uint32_t)lane >> 4) & 1) * 8) * PITCH) * 2
                          + (((uint32_t)lane >> 3) & 1) * 16;
    const int phb = (wid >> 2) * U_SZ;

    uint32_t ah[16][4];
#pragma unroll
    for (int kk = 0; kk < 16; ++kk)
        LDMX4(ah[kk][0], ah[kk][1], ah[kk][2], ah[kk][3],
              smem_u + SA + a_off + (uint32_t)kk * 32);

    float pl0 = 0.f, pl1 = 0.f;

    // ==================== chunk loop (no __syncthreads) ====================
    for (int c = 0; c < N_CHUNKS; ++c) {
        MBARRIER_WAIT_PARITY(smem_u + SMBAR + 8 * (c & 1), (c >> 1) & 1);
        const uint32_t bbase = smem_u + SB + (c & 1) * BUF_STRIDE;

        float acc[4][4];
#pragma unroll
        for (int j = 0; j < 4; ++j)
#pragma unroll
            for (int r = 0; r < 4; ++r) acc[j][r] = 0.f;

#pragma unroll
        for (int kk = 0; kk < 16; ++kk) {
            const uint32_t koff = (uint32_t)kk * 32;
#pragma unroll
            for (int j2 = 0; j2 < 2; ++j2) {
                uint32_t b0r, b1r, b2r, b3r;
                LDMX4(b0r, b1r, b2r, b3r,
                      bbase + b4_off + (uint32_t)j2 * (16 * PITCH * 2) + koff);
                const int j = j2 * 2;
                MMA16816(acc[j],     ah[kk][0], ah[kk][1], ah[kk][2], ah[kk][3], b0r, b1r);
                MMA16816(acc[j + 1], ah[kk][0], ah[kk][1], ah[kk][2], ah[kk][3], b2r, b3r);
            }
        }

        // fused epilogue (acc consumed -> all LDSM reads of this buffer done)
#pragma unroll
        for (int j = 0; j < 4; ++j) {
            const int u = c * 32 + j * 8 + (lane & 3) * 2;
            const float ph0 = ph_s[phb + u],     vv0 = V_s[u];
            const float ph1 = ph_s[phb + u + 1], vv1 = V_s[u + 1];
            pl0 = fmaf(vv0, tanh_fast(acc[j][0] + ph0), pl0);
            pl0 = fmaf(vv1, tanh_fast(acc[j][1] + ph1), pl0);
            pl1 = fmaf(vv0, tanh_fast(acc[j][2] + ph0), pl1);
            pl1 = fmaf(vv1, tanh_fast(acc[j][3] + ph1), pl1);
        }

        // signal this warp is done with buffer (c&1)
        if (lane == 0) MBARRIER_ARRIVE(smem_u + SMBAR + 16 + 8 * (c & 1));

        // producer: refill buffer (c&1) for chunk c+2 once all 8 warps done
        if (tid == 0 && c + 2 < N_CHUNKS) {
            MBARRIER_WAIT_PARITY(smem_u + SMBAR + 16 + 8 * (c & 1), (c >> 1) & 1);
            const uint32_t mbn = smem_u + SMBAR + 8 * (c & 1);
            MBARRIER_EXPECT_TX(mbn, CH_BYTES);
            BULK_G2S(smem_u + SB + (c & 1) * BUF_STRIDE,
                     g_w1t + (size_t)(c + 2) * CH_BYTES, CH_BYTES, mbn);
        }
    }

    // ---- reduce logit partials across the 4 lanes sharing a row ----
    pl0 += __shfl_xor_sync(0xffffffffu, pl0, 1);
    pl0 += __shfl_xor_sync(0xffffffffu, pl0, 2);
    pl1 += __shfl_xor_sync(0xffffffffu, pl1, 1);
    pl1 += __shfl_xor_sync(0xffffffffu, pl1, 2);
    if ((lane & 3) == 0) {
        w_s[m0 + (lane >> 2)]     = pl0;
        w_s[m0 + 8 + (lane >> 2)] = pl1;
    }
    __syncthreads();

    // ---- softmax per batch over L=64 (warps 0-3; bV shift-invariant) ----
    {
        const bool act = wid < 4;
        const int bb = (wid >> 1) & 1;
        const int li = (wid & 1) * 32 + lane;
        float lv = act ? w_s[bb * 64 + li] : -1e30f;
        float m = lv;
#pragma unroll
        for (int off = 16; off; off >>= 1)
            m = fmaxf(m, __shfl_xor_sync(0xffffffffu, m, off));
        if (act && lane == 0) red_s[wid] = m;
        __syncthreads();
        const float mx = fmaxf(red_s[bb * 2], red_s[bb * 2 + 1]);
        float e = act ? expf(lv - mx) : 0.f;
        float s = e;
#pragma unroll
        for (int off = 16; off; off >>= 1)
            s += __shfl_xor_sync(0xffffffffu, s, off);
        if (act && lane == 0) red_s[4 + wid] = s;
        __syncthreads();
        if (act) w_s[bb * 64 + li] = e / (red_s[4 + bb * 2] + red_s[5 + bb * 2]);
        __syncthreads();
    }

    // ---- context from fp32 gmem features (L2-hot): exact path ----
    {
        const int d = tid;
#pragma unroll
        for (int bb = 0; bb < 2; ++bb) {
            const float* frow = features + (size_t)(b0 + bb) * L_SZ * D_SZ + d;
            float cacc = 0.f;
#pragma unroll 8
            for (int l = 0; l < 64; ++l)
                cacc = fmaf(w_s[bb * 64 + l], __ldg(frow + l * D_SZ), cacc);
            if (ctx_out) ctx_out[(size_t)(b0 + bb) * D_SZ + d] = cacc;
        }
        if (w_out && tid < 128) w_out[(size_t)b0 * L_SZ + tid] = w_s[tid];
    }

    __syncthreads();
    if (tid == 0) {
        MBARRIER_INVAL(smem_u + SMBAR);
        MBARRIER_INVAL(smem_u + SMBAR + 8);
        MBARRIER_INVAL(smem_u + SMBAR + 16);
        MBARRIER_INVAL(smem_u + SMBAR + 24);
    }
}

// ---------------------------------------------------------------------------
extern "C" void kernel_launch(void* const* d_in, const int* in_sizes, int n_in,
                              void* d_out, int out_size)
{
    const float* features = (const float*)d_in[0];
    const float* hidden   = (const float*)d_in[1];
    const float* W1       = (const float*)d_in[2];
    const float* b1       = (const float*)d_in[3];
    const float* W2       = (const float*)d_in[4];
    const float* b2       = (const float*)d_in[5];
    const float* V        = (const float*)d_in[6];
    // d_in[7] = bV: softmax shift-invariant -> no output effect.

    float* out = (float*)d_out;
    float* ctx_out = nullptr;
    float* w_out   = nullptr;
    const int CTX_N = B_SZ * D_SZ;
    const int W_N   = B_SZ * L_SZ;
    if (out_size >= CTX_N + W_N) { ctx_out = out; w_out = out + CTX_N; }
    else if (out_size == CTX_N)  { ctx_out = out; }
    else if (out_size == W_N)    { w_out = out; }
    else                         { ctx_out = out; }

    prep_all_kernel<<<B_SZ + D_SZ + U_SZ, 256>>>(hidden, W1, W2);

    cudaFuncSetAttribute(proj_mma_kernel,
                         cudaFuncAttributeMaxDynamicSharedMemorySize, P_SMEM);
    proj_mma_kernel<<<128, 256, P_SMEM>>>(b1, b2);

    cudaFuncSetAttribute(attn_mma_kernel,
                         cudaFuncAttributeMaxDynamicSharedMemorySize, SMEM_TOTAL);
    attn_mma_kernel<<<B_SZ / 2, 256, SMEM_TOTAL>>>(features, V, ctx_out, w_out);
}

// round 10
// speedup vs baseline: 2.7933x; 1.1003x over previous
#include <cuda_runtime.h>
#include <cuda_fp16.h>
#include <math.h>
#include <stdint.h>

#define B_SZ 2048
#define L_SZ 64
#define D_SZ 256
#define U_SZ 512

// ---- attn tiling ----
#define PITCH 264                        // fp16 elems/row (256+8): conflict-free LDSM
#define CH_ROWS 32
#define N_CHUNKS 16
#define CH_BYTES (CH_ROWS * PITCH * 2)   // 16896

// ---- proj tiling (K = 512) ----
#define PITCH2 520                       // 512+8
#define CH2_BYTES (32 * PITCH2 * 2)      // 33280
#define A2_BYTES (128 * PITCH2 * 2)      // 133120

// ---------------------------------------------------------------------------
// PTX helpers (base-PTX only; compiles under compute_103)
// ---------------------------------------------------------------------------
__device__ __forceinline__ uint32_t smem_to_u32(const void* p) {
    uint32_t a;
    asm("{ .reg .u64 t; cvta.to.shared.u64 t, %1; cvt.u32.u64 %0, t; }"
        : "=r"(a) : "l"(p));
    return a;
}

#define MBARRIER_INIT(mb, c) \
    asm volatile("mbarrier.init.shared.b64 [%0], %1;" \
                 :: "r"((uint32_t)(mb)), "r"((uint32_t)(c)) : "memory")
#define MBARRIER_INVAL(mb) \
    asm volatile("mbarrier.inval.shared.b64 [%0];" :: "r"((uint32_t)(mb)) : "memory")
#define MBARRIER_EXPECT_TX(mb, bytes) \
    asm volatile("mbarrier.arrive.expect_tx.shared.b64 _, [%0], %1;" \
                 :: "r"((uint32_t)(mb)), "r"((uint32_t)(bytes)) : "memory")
#define MBARRIER_ARRIVE(mb) \
    asm volatile("mbarrier.arrive.shared.b64 _, [%0];" \
                 :: "r"((uint32_t)(mb)) : "memory")

#define MBARRIER_WAIT_PARITY(mb, ph) do { \
    uint32_t _mb = (uint32_t)(mb); uint32_t _p = (uint32_t)(ph); uint32_t _done; \
    asm volatile("{\n\t.reg .pred p;\n\t" \
        "mbarrier.try_wait.parity.acquire.cta.shared::cta.b64 p, [%1], %2;\n\t" \
        "selp.b32 %0, 1, 0, p;\n\t}" : "=r"(_done) : "r"(_mb), "r"(_p) : "memory"); \
    if (!_done) { \
        asm volatile("{\n\t.reg .pred P1;\n\t" \
            "WL_%=:\n\t" \
            "mbarrier.try_wait.parity.acquire.cta.shared::cta.b64 P1, [%0], %1, 0x989680;\n\t" \
            "@P1 bra.uni WD_%=;\n\t" \
            "bra.uni WL_%=;\n\t" \
            "WD_%=:\n\t}" :: "r"(_mb), "r"(_p) : "memory"); \
    } \
} while (0)

#define BULK_G2S(dst, src, sz, mb) \
    asm volatile("cp.async.bulk.shared::cluster.global.mbarrier::complete_tx::bytes " \
                 "[%0], [%1], %2, [%3];" \
                 :: "r"((uint32_t)(dst)), "l"(src), "r"((uint32_t)(sz)), \
                    "r"((uint32_t)(mb)) : "memory")

#define LDMX4(r0, r1, r2, r3, addr) \
    asm volatile("ldmatrix.sync.aligned.m8n8.x4.shared.b16 {%0,%1,%2,%3}, [%4];" \
                 : "=r"(r0), "=r"(r1), "=r"(r2), "=r"(r3) : "r"(addr))

#define MMA16816(c, a0, a1, a2, a3, b0, b1) \
    asm volatile("mma.sync.aligned.m16n8k16.row.col.f32.f16.f16.f32 " \
                 "{%0,%1,%2,%3},{%4,%5,%6,%7},{%8,%9},{%0,%1,%2,%3};" \
                 : "+f"((c)[0]), "+f"((c)[1]), "+f"((c)[2]), "+f"((c)[3]) \
                 : "r"(a0), "r"(a1), "r"(a2), "r"(a3), "r"(b0), "r"(b1))

__device__ __forceinline__ float tanh_fast(float x) {
    float e = __expf(2.f * x);
    return 1.f - __fdividef(2.f, e + 1.f);
}

// ---------------------------------------------------------------------------
// Device scratch (allocation-free)
// ---------------------------------------------------------------------------
__device__ float g_ph[B_SZ * U_SZ];
__device__ __align__(16) unsigned char g_w1t[N_CHUNKS * CH_BYTES];   // W1^T fp16 chunks
__device__ __align__(16) unsigned char g_w2t[16 * CH2_BYTES];        // W2^T fp16 chunks
__device__ __align__(16) unsigned char g_h16[B_SZ * PITCH2 * 2];     // hidden fp16 pitched

// ---------------------------------------------------------------------------
// Prep v2: smem-tiled transposes, coalesced on BOTH sides.
//   blocks [0, 1024):            hidden rows (2 rows/block, straight convert)
//   blocks [1024, 1088):         W1^T  (16 u-tiles x 4 d-tiles, 32u x 64d)
//   blocks [1088, 1216):         W2^T  (16 n-tiles x 8 k-tiles, 32n x 64k)
// ---------------------------------------------------------------------------
__global__ void prep_all_kernel(const float* __restrict__ hidden,
                                const float* __restrict__ W1,
                                const float* __restrict__ W2)
{
    __shared__ float s[32][66];
    const int bid = blockIdx.x;
    const int tid = threadIdx.x;

    if (bid < 1024) {                               // hidden: rows 2b, 2b+1
        const int b = bid * 2;
#pragma unroll
        for (int rr = 0; rr < 2; ++rr) {
            const float4 v = ((const float4*)(hidden + (size_t)(b + rr) * U_SZ))[tid & 127];
            // 128 float4 per row; 256 threads -> 2 rows handled by tid>>7
            const int row = b + (tid >> 7);
            if (rr == (tid >> 7) || true) {}        // (keep simple: do both rows below)
        }
        // simpler: 256 threads = 2 rows x 128 float4
        const int row = b + (tid >> 7);
        const int c4  = tid & 127;
        const float4 v = ((const float4*)(hidden + (size_t)row * U_SZ))[c4];
        __half2 h0 = __float22half2_rn(make_float2(v.x, v.y));
        __half2 h1 = __float22half2_rn(make_float2(v.z, v.w));
        *(uint2*)(g_h16 + ((size_t)row * PITCH2 + c4 * 4) * 2) =
            make_uint2(*(uint32_t*)&h0, *(uint32_t*)&h1);
    } else if (bid < 1088) {                        // W1^T tile
        const int t  = bid - 1024;
        const int u0 = (t & 15) * 32;               // u-tile (== chunk*32)
        const int d0 = (t >> 4) * 64;               // d-tile
        // load: W1[d0+dd][u0+uu], coalesced along u
        const int uu = tid & 31, dd0 = tid >> 5;    // 8 d-rows per pass
#pragma unroll
        for (int i = 0; i < 8; ++i)
            s[uu][dd0 + 8 * i] = W1[(size_t)(d0 + dd0 + 8 * i) * U_SZ + u0 + uu];
        __syncthreads();
        // store: g_w1t[chunk][n=uu][d], coalesced along d (half2)
        const int chunk = u0 >> 5;
        const int dc = tid & 31;                    // half2 index (64 d / 2)
        const int r0 = tid >> 5;
#pragma unroll
        for (int i = 0; i < 4; ++i) {
            const int r = r0 + 8 * i;
            __half2 h = __floats2half2_rn(s[r][dc * 2], s[r][dc * 2 + 1]);
            *(__half2*)(g_w1t + (size_t)chunk * CH_BYTES +
                        ((size_t)r * PITCH + d0 + dc * 2) * 2) = h;
        }
    } else {                                        // W2^T tile
        const int t  = bid - 1088;
        const int n0 = (t & 15) * 32;               // n-tile (== chunk*32)
        const int k0 = (t >> 4) * 64;               // k-tile
        const int nn = tid & 31, kk0 = tid >> 5;
#pragma unroll
        for (int i = 0; i < 8; ++i)
            s[nn][kk0 + 8 * i] = W2[(size_t)(k0 + kk0 + 8 * i) * U_SZ + n0 + nn];
        __syncthreads();
        const int chunk = n0 >> 5;
        const int kc = tid & 31;
        const int r0 = tid >> 5;
#pragma unroll
        for (int i = 0; i < 4; ++i) {
            const int r = r0 + 8 * i;
            __half2 h = __floats2half2_rn(s[r][kc * 2], s[r][kc * 2 + 1]);
            *(__half2*)(g_w2t + (size_t)chunk * CH2_BYTES +
                        ((size_t)r * PITCH2 + k0 + kc * 2) * 2) = h;
        }
    }
}

// ---------------------------------------------------------------------------
// proj via tensor cores: g_ph[m][u] = hidden[m,:].W2[:,u] + b1[u] + b2[u]
static constexpr int P_SA    = 0;
static constexpr int P_SB    = A2_BYTES;               // 133120
static constexpr int P_SBIAS = P_SB + 2 * CH2_BYTES;   // 199680
static constexpr int P_SMBAR = P_SBIAS + 256;          // 199936
static constexpr int P_SMEM  = P_SMBAR + 64;           // 200000
// ---------------------------------------------------------------------------
__global__ void __launch_bounds__(256, 1)
proj_mma_kernel(const float* __restrict__ b1, const float* __restrict__ b2)
{
    extern __shared__ __align__(1024) char smem[];
    const uint32_t smem_u = smem_to_u32(smem);
    const int tid  = threadIdx.x;
    const int wid  = tid >> 5;
    const int lane = tid & 31;
    const int mq   = blockIdx.x >> 3;
    const int nq   = blockIdx.x & 7;

    float* sbias = (float*)(smem + P_SBIAS);

    if (tid == 0) {
        MBARRIER_INIT(smem_u + P_SMBAR, 1);
        MBARRIER_INIT(smem_u + P_SMBAR + 8, 1);
        MBARRIER_INIT(smem_u + P_SMBAR + 16, 1);
        MBARRIER_EXPECT_TX(smem_u + P_SMBAR, A2_BYTES);
        BULK_G2S(smem_u + P_SA, g_h16 + (size_t)mq * A2_BYTES, A2_BYTES,
                 smem_u + P_SMBAR);
#pragma unroll
        for (int c = 0; c < 2; ++c) {
            MBARRIER_EXPECT_TX(smem_u + P_SMBAR + 8 + 8 * c, CH2_BYTES);
            BULK_G2S(smem_u + P_SB + c * CH2_BYTES,
                     g_w2t + (size_t)(nq * 2 + c) * CH2_BYTES, CH2_BYTES,
                     smem_u + P_SMBAR + 8 + 8 * c);
        }
    }
    if (tid < 64) sbias[tid] = b1[nq * 64 + tid] + b2[nq * 64 + tid];
    __syncthreads();

    MBARRIER_WAIT_PARITY(smem_u + P_SMBAR, 0);

    const uint32_t a_row = (uint32_t)(wid * 16 + (lane & 7) + ((lane >> 3) & 1) * 8);
    const uint32_t a_off = (a_row * PITCH2 + ((uint32_t)(lane >> 4)) * 8) * 2;
    const uint32_t b4_off = (((uint32_t)(lane & 7) + (((uint32_t)lane >> 4) & 1) * 8) * PITCH2) * 2
                          + (((uint32_t)lane >> 3) & 1) * 16;

    uint32_t ah[32][4];
#pragma unroll
    for (int kk = 0; kk < 32; ++kk)
        LDMX4(ah[kk][0], ah[kk][1], ah[kk][2], ah[kk][3],
              smem_u + P_SA + a_off + (uint32_t)kk * 32);

#pragma unroll
    for (int c = 0; c < 2; ++c) {
        MBARRIER_WAIT_PARITY(smem_u + P_SMBAR + 8 + 8 * c, 0);
        const uint32_t bbase = smem_u + P_SB + c * CH2_BYTES;

        float acc[4][4];
#pragma unroll
        for (int j = 0; j < 4; ++j)
#pragma unroll
            for (int r = 0; r < 4; ++r) acc[j][r] = 0.f;

#pragma unroll
        for (int kk = 0; kk < 32; ++kk) {
            const uint32_t koff = (uint32_t)kk * 32;
#pragma unroll
            for (int j2 = 0; j2 < 2; ++j2) {
                uint32_t b0r, b1r, b2r, b3r;
                LDMX4(b0r, b1r, b2r, b3r,
                      bbase + b4_off + (uint32_t)j2 * (16 * PITCH2 * 2) + koff);
                const int j = j2 * 2;
                MMA16816(acc[j],     ah[kk][0], ah[kk][1], ah[kk][2], ah[kk][3], b0r, b1r);
                MMA16816(acc[j + 1], ah[kk][0], ah[kk][1], ah[kk][2], ah[kk][3], b2r, b3r);
            }
        }

#pragma unroll
        for (int j = 0; j < 4; ++j) {
            const int ul = c * 32 + j * 8 + (lane & 3) * 2;
            const int ug = nq * 64 + ul;
            const int m  = mq * 128 + wid * 16 + (lane >> 2);
            float2 v0 = make_float2(acc[j][0] + sbias[ul], acc[j][1] + sbias[ul + 1]);
            float2 v1 = make_float2(acc[j][2] + sbias[ul], acc[j][3] + sbias[ul + 1]);
            *(float2*)&g_ph[(size_t)m * U_SZ + ug]       = v0;
            *(float2*)&g_ph[(size_t)(m + 8) * U_SZ + ug] = v1;
        }
    }

    __syncthreads();
    if (tid == 0) {
        MBARRIER_INVAL(smem_u + P_SMBAR);
        MBARRIER_INVAL(smem_u + P_SMBAR + 8);
        MBARRIER_INVAL(smem_u + P_SMBAR + 16);
    }
}

// ---------------------------------------------------------------------------
// Main fused attention: 1 CTA = 2 batches (M=128), 8 warps x 16 rows.
static constexpr int SA    = 0;                       // 67584 (A fp16)
static constexpr int SB    = 67584;                   // 2 bufs x 16896
static constexpr int BUF_STRIDE = CH_BYTES;
static constexpr int SPH   = 101376;                  // 4096
static constexpr int SV    = 105472;                  // 2048
static constexpr int SW    = 107520;                  // 512
static constexpr int SRED  = 108032;                  // 64
static constexpr int SMBAR = 108096;                  // full[2] + empty[2]
static constexpr int SMEM_TOTAL = 108160;
// ---------------------------------------------------------------------------
__global__ void __launch_bounds__(256, 2)
attn_mma_kernel(const float* __restrict__ features,
                const float* __restrict__ V,
                float* __restrict__ ctx_out,
                float* __restrict__ w_out)
{
    extern __shared__ __align__(1024) char smem[];
    const uint32_t smem_u = smem_to_u32(smem);
    const int tid  = threadIdx.x;
    const int wid  = tid >> 5;
    const int lane = tid & 31;
    const int b0   = blockIdx.x * 2;

    float* ph_s  = (float*)(smem + SPH);
    float* V_s   = (float*)(smem + SV);
    float* w_s   = (float*)(smem + SW);
    float* red_s = (float*)(smem + SRED);

    if (tid == 0) {
        MBARRIER_INIT(smem_u + SMBAR, 1);          // full 0
        MBARRIER_INIT(smem_u + SMBAR + 8, 1);      // full 1
        MBARRIER_INIT(smem_u + SMBAR + 16, 8);     // empty 0 (8 warps)
        MBARRIER_INIT(smem_u + SMBAR + 24, 8);     // empty 1
#pragma unroll
        for (int c = 0; c < 2; ++c) {
            const uint32_t mb = smem_u + SMBAR + 8 * c;
            MBARRIER_EXPECT_TX(mb, CH_BYTES);
            BULK_G2S(smem_u + SB + c * BUF_STRIDE,
                     g_w1t + (size_t)c * CH_BYTES, CH_BYTES, mb);
        }
    }

    // ---- Stage features[b0..b0+1] as fp16 (padded rows) ----
    {
        const float4* fsrc = (const float4*)(features + (size_t)b0 * L_SZ * D_SZ);
#pragma unroll 4
        for (int t = 0; t < 32; ++t) {
            const int idx = tid + 256 * t;
            const int row = idx >> 6;
            const int d   = (idx & 63) * 4;
            const float4 v = fsrc[idx];
            __half2 h0 = __float22half2_rn(make_float2(v.x, v.y));
            __half2 h1 = __float22half2_rn(make_float2(v.z, v.w));
            const uint32_t off = ((uint32_t)row * PITCH + d) * 2;
            *(uint2*)(smem + SA + off) =
                make_uint2(*(uint32_t*)&h0, *(uint32_t*)&h1);
        }
    }
#pragma unroll
    for (int t = 0; t < 4; ++t)
        ph_s[tid + 256 * t] = g_ph[(size_t)b0 * U_SZ + tid + 256 * t];
    V_s[tid]       = V[tid];
    V_s[tid + 256] = V[tid + 256];
    __syncthreads();

    const int m0 = wid * 16;
    const uint32_t a_row = (uint32_t)(m0 + (lane & 7) + ((lane >> 3) & 1) * 8);
    const uint32_t a_off = (a_row * PITCH + ((uint32_t)(lane >> 4)) * 8) * 2;
    const uint32_t b4_off = (((uint32_t)(lane & 7) + (((uint32_t)lane >> 4) & 1) * 8) * PITCH) * 2
                          + (((uint32_t)lane >> 3) & 1) * 16;
    const int phb = (wid >> 2) * U_SZ;

    uint32_t ah[16][4];
#pragma unroll
    for (int kk = 0; kk < 16; ++kk)
        LDMX4(ah[kk][0], ah[kk][1], ah[kk][2], ah[kk][3],
              smem_u + SA + a_off + (uint32_t)kk * 32);

    float pl0 = 0.f, pl1 = 0.f;

    // ==================== chunk loop (mbarrier pipeline) ====================
    for (int c = 0; c < N_CHUNKS; ++c) {
        MBARRIER_WAIT_PARITY(smem_u + SMBAR + 8 * (c & 1), (c >> 1) & 1);
        const uint32_t bbase = smem_u + SB + (c & 1) * BUF_STRIDE;

        float acc[4][4];
#pragma unroll
        for (int j = 0; j < 4; ++j)
#pragma unroll
            for (int r = 0; r < 4; ++r) acc[j][r] = 0.f;

#pragma unroll
        for (int kk = 0; kk < 16; ++kk) {
            const uint32_t koff = (uint32_t)kk * 32;
#pragma unroll
            for (int j2 = 0; j2 < 2; ++j2) {
                uint32_t b0r, b1r, b2r, b3r;
                LDMX4(b0r, b1r, b2r, b3r,
                      bbase + b4_off + (uint32_t)j2 * (16 * PITCH * 2) + koff);
                const int j = j2 * 2;
                MMA16816(acc[j],     ah[kk][0], ah[kk][1], ah[kk][2], ah[kk][3], b0r, b1r);
                MMA16816(acc[j + 1], ah[kk][0], ah[kk][1], ah[kk][2], ah[kk][3], b2r, b3r);
            }
        }

#pragma unroll
        for (int j = 0; j < 4; ++j) {
            const int u = c * 32 + j * 8 + (lane & 3) * 2;
            const float ph0 = ph_s[phb + u],     vv0 = V_s[u];
            const float ph1 = ph_s[phb + u + 1], vv1 = V_s[u + 1];
            pl0 = fmaf(vv0, tanh_fast(acc[j][0] + ph0), pl0);
            pl0 = fmaf(vv1, tanh_fast(acc[j][1] + ph1), pl0);
            pl1 = fmaf(vv0, tanh_fast(acc[j][2] + ph0), pl1);
            pl1 = fmaf(vv1, tanh_fast(acc[j][3] + ph1), pl1);
        }

        if (lane == 0) MBARRIER_ARRIVE(smem_u + SMBAR + 16 + 8 * (c & 1));

        if (tid == 0 && c + 2 < N_CHUNKS) {
            MBARRIER_WAIT_PARITY(smem_u + SMBAR + 16 + 8 * (c & 1), (c >> 1) & 1);
            const uint32_t mbn = smem_u + SMBAR + 8 * (c & 1);
            MBARRIER_EXPECT_TX(mbn, CH_BYTES);
            BULK_G2S(smem_u + SB + (c & 1) * BUF_STRIDE,
                     g_w1t + (size_t)(c + 2) * CH_BYTES, CH_BYTES, mbn);
        }
    }

    // ---- reduce logit partials across the 4 lanes sharing a row ----
    pl0 += __shfl_xor_sync(0xffffffffu, pl0, 1);
    pl0 += __shfl_xor_sync(0xffffffffu, pl0, 2);
    pl1 += __shfl_xor_sync(0xffffffffu, pl1, 1);
    pl1 += __shfl_xor_sync(0xffffffffu, pl1, 2);
    if ((lane & 3) == 0) {
        w_s[m0 + (lane >> 2)]     = pl0;
        w_s[m0 + 8 + (lane >> 2)] = pl1;
    }
    __syncthreads();

    // ---- softmax per batch over L=64 (warps 0-3; bV shift-invariant) ----
    {
        const bool act = wid < 4;
        const int bb = (wid >> 1) & 1;
        const int li = (wid & 1) * 32 + lane;
        float lv = act ? w_s[bb * 64 + li] : -1e30f;
        float m = lv;
#pragma unroll
        for (int off = 16; off; off >>= 1)
            m = fmaxf(m, __shfl_xor_sync(0xffffffffu, m, off));
        if (act && lane == 0) red_s[wid] = m;
        __syncthreads();
        const float mx = fmaxf(red_s[bb * 2], red_s[bb * 2 + 1]);
        float e = act ? expf(lv - mx) : 0.f;
        float s = e;
#pragma unroll
        for (int off = 16; off; off >>= 1)
            s += __shfl_xor_sync(0xffffffffu, s, off);
        if (act && lane == 0) red_s[4 + wid] = s;
        __syncthreads();
        if (act) w_s[bb * 64 + li] = e / (red_s[4 + bb * 2] + red_s[5 + bb * 2]);
        __syncthreads();
    }

    // ---- context from resident fp16 A-tile (LDS-hot; err ~2.4e-4 RMS) ----
    {
        const int d = tid;
#pragma unroll
        for (int bb = 0; bb < 2; ++bb) {
            float cacc = 0.f;
#pragma unroll 8
            for (int l = 0; l < 64; ++l) {
                const int row = bb * 64 + l;
                const float f = __half2float(
                    *(const __half*)(smem + SA + ((uint32_t)row * PITCH + d) * 2));
                cacc = fmaf(w_s[bb * 64 + l], f, cacc);
            }
            if (ctx_out) ctx_out[(size_t)(b0 + bb) * D_SZ + d] = cacc;
        }
        if (w_out && tid < 128) w_out[(size_t)b0 * L_SZ + tid] = w_s[tid];
    }

    __syncthreads();
    if (tid == 0) {
        MBARRIER_INVAL(smem_u + SMBAR);
        MBARRIER_INVAL(smem_u + SMBAR + 8);
        MBARRIER_INVAL(smem_u + SMBAR + 16);
        MBARRIER_INVAL(smem_u + SMBAR + 24);
    }
}

// ---------------------------------------------------------------------------
extern "C" void kernel_launch(void* const* d_in, const int* in_sizes, int n_in,
                              void* d_out, int out_size)
{
    const float* features = (const float*)d_in[0];
    const float* hidden   = (const float*)d_in[1];
    const float* W1       = (const float*)d_in[2];
    const float* b1       = (const float*)d_in[3];
    const float* W2       = (const float*)d_in[4];
    const float* b2       = (const float*)d_in[5];
    const float* V        = (const float*)d_in[6];
    // d_in[7] = bV: softmax shift-invariant -> no output effect.

    float* out = (float*)d_out;
    float* ctx_out = nullptr;
    float* w_out   = nullptr;
    const int CTX_N = B_SZ * D_SZ;
    const int W_N   = B_SZ * L_SZ;
    if (out_size >= CTX_N + W_N) { ctx_out = out; w_out = out + CTX_N; }
    else if (out_size == CTX_N)  { ctx_out = out; }
    else if (out_size == W_N)    { w_out = out; }
    else                         { ctx_out = out; }

    prep_all_kernel<<<1216, 256>>>(hidden, W1, W2);

    cudaFuncSetAttribute(proj_mma_kernel,
                         cudaFuncAttributeMaxDynamicSharedMemorySize, P_SMEM);
    proj_mma_kernel<<<128, 256, P_SMEM>>>(b1, b2);

    cudaFuncSetAttribute(attn_mma_kernel,
                         cudaFuncAttributeMaxDynamicSharedMemorySize, SMEM_TOTAL);
    attn_mma_kernel<<<B_SZ / 2, 256, SMEM_TOTAL>>>(features, V, ctx_out, w_out);
}